// round 1
// baseline (speedup 1.0000x reference)
#include <cuda_runtime.h>
#include <math.h>

// Problem constants
#define Bb 8
#define Nn 2048
#define Tt 12
#define Dd 256
#define Hh 8
#define DK 32
#define Mm 8
#define ROWS (Bb * Nn * Tt)          // 196608
#define BN_CNT (Bb * Nn)             // 16384

// Scratch (device globals; allocation-free rule)
__device__ float g_q[ROWS * Dd];
__device__ float g_k[ROWS * Dd];
__device__ float g_v[ROWS * Dd];
__device__ float g_attn[ROWS * Dd];
__device__ float g_fc[ROWS * Dd];

// ----------------------------------------------------------------------------
// Tiled fp32 GEMM:  C[m][n] = sum_k A[m][k] * W[n][k] + bias[n]
// A: [ROWS, 256] row-major, W: [256, 256] row-major (contraction over 2nd dim)
// BM=BN=64, BK=16, 256 threads, 4x4 microtile per thread.
// ----------------------------------------------------------------------------
__global__ __launch_bounds__(256) void gemm_bias_kernel(
    const float* __restrict__ A, const float* __restrict__ W,
    const float* __restrict__ bias, float* __restrict__ C)
{
    const int K = 256;
    __shared__ float As[16][68];   // [k][m], pad to 68 for conflict/alignment
    __shared__ float Bs[16][68];   // [k][n]

    const int m0 = blockIdx.x * 64;
    const int n0 = blockIdx.y * 64;
    const int tid = threadIdx.x;
    const int tx = tid & 15;       // 0..15  -> n
    const int ty = tid >> 4;       // 0..15  -> m
    const int lr = ty;             // load row within 16-row group
    const int lc = tx;             // load k within tile

    float acc[4][4];
    #pragma unroll
    for (int i = 0; i < 4; i++)
        #pragma unroll
        for (int j = 0; j < 4; j++) acc[i][j] = 0.f;

    for (int k0 = 0; k0 < K; k0 += 16) {
        #pragma unroll
        for (int i = 0; i < 4; i++) {
            As[lc][lr + i * 16] = A[(size_t)(m0 + lr + i * 16) * K + k0 + lc];
            Bs[lc][lr + i * 16] = W[(size_t)(n0 + lr + i * 16) * K + k0 + lc];
        }
        __syncthreads();
        #pragma unroll
        for (int k = 0; k < 16; k++) {
            float4 a4 = *(const float4*)&As[k][ty * 4];
            float4 b4 = *(const float4*)&Bs[k][tx * 4];
            float a[4] = {a4.x, a4.y, a4.z, a4.w};
            float b[4] = {b4.x, b4.y, b4.z, b4.w};
            #pragma unroll
            for (int i = 0; i < 4; i++)
                #pragma unroll
                for (int j = 0; j < 4; j++)
                    acc[i][j] += a[i] * b[j];
        }
        __syncthreads();
    }

    #pragma unroll
    for (int i = 0; i < 4; i++) {
        int m = m0 + ty * 4 + i;
        #pragma unroll
        for (int j = 0; j < 4; j++) {
            int n = n0 + tx * 4 + j;
            C[(size_t)m * Dd + n] = acc[i][j] + bias[n];
        }
    }
}

// ----------------------------------------------------------------------------
// Attention kernel: one block per (b, n). Handles all heads, causal temporal
// attention over T=12 plus memory-bank attention (M=8), sigmoid-gated fusion.
// ----------------------------------------------------------------------------
__global__ __launch_bounds__(256) void attn_kernel(
    const float* __restrict__ Q, const float* __restrict__ K,
    const float* __restrict__ V,
    const float* __restrict__ mem_k, const float* __restrict__ mem_v,
    const float* __restrict__ alpha_l, float* __restrict__ out)
{
    __shared__ float Qs[Tt * Dd];
    __shared__ float Ks[Tt * Dd];
    __shared__ float Vs[Tt * Dd];
    __shared__ float sc[Hh][Tt][Tt];     // time scores -> probs
    __shared__ float scl[Hh][Tt][Mm];    // memory scores -> probs

    const int tid = threadIdx.x;
    const size_t base = (size_t)blockIdx.x * (Tt * Dd);

    for (int i = tid; i < Tt * Dd; i += 256) {
        Qs[i] = Q[base + i];
        Ks[i] = K[base + i];
        Vs[i] = V[base + i];
    }
    __syncthreads();

    const float scale = 0.1767766952966369f;  // 1/sqrt(32)

    // temporal scores: H*T*T = 1152 entries
    for (int idx = tid; idx < Hh * Tt * Tt; idx += 256) {
        int h = idx / (Tt * Tt);
        int r = idx % (Tt * Tt);
        int t = r / Tt, s = r % Tt;
        float v = -1e30f;
        if (s <= t) {
            const float* q = &Qs[t * Dd + h * DK];
            const float* k = &Ks[s * Dd + h * DK];
            float acc = 0.f;
            #pragma unroll
            for (int d = 0; d < DK; d++) acc += q[d] * k[d];
            v = acc * scale;
        }
        sc[h][t][s] = v;
    }
    // memory scores: H*T*M = 768 entries
    for (int idx = tid; idx < Hh * Tt * Mm; idx += 256) {
        int h = idx / (Tt * Mm);
        int r = idx % (Tt * Mm);
        int t = r / Mm, m = r % Mm;
        const float* q  = &Qs[t * Dd + h * DK];
        const float* mk = &mem_k[(h * Mm + m) * DK];
        float acc = 0.f;
        #pragma unroll
        for (int d = 0; d < DK; d++) acc += q[d] * mk[d];
        scl[h][t][m] = acc * scale;
    }
    __syncthreads();

    // softmax: 96 time rows + 96 memory rows
    if (tid < Hh * Tt) {
        int h = tid / Tt, t = tid % Tt;
        float mx = -1e30f;
        for (int s = 0; s <= t; s++) mx = fmaxf(mx, sc[h][t][s]);
        float sum = 0.f;
        for (int s = 0; s <= t; s++) { float e = expf(sc[h][t][s] - mx); sc[h][t][s] = e; sum += e; }
        float inv = 1.f / sum;
        for (int s = 0; s <= t; s++) sc[h][t][s] *= inv;
        for (int s = t + 1; s < Tt; s++) sc[h][t][s] = 0.f;
    } else if (tid < 2 * Hh * Tt) {
        int r = tid - Hh * Tt;
        int h = r / Tt, t = r % Tt;
        float mx = -1e30f;
        #pragma unroll
        for (int m = 0; m < Mm; m++) mx = fmaxf(mx, scl[h][t][m]);
        float sum = 0.f;
        #pragma unroll
        for (int m = 0; m < Mm; m++) { float e = expf(scl[h][t][m] - mx); scl[h][t][m] = e; sum += e; }
        float inv = 1.f / sum;
        #pragma unroll
        for (int m = 0; m < Mm; m++) scl[h][t][m] *= inv;
    }
    __syncthreads();

    const float wl = 1.f / (1.f + expf(-alpha_l[0]));
    const float wt = 1.f - wl;

    // outputs: T*D = 3072 values
    for (int i = tid; i < Tt * Dd; i += 256) {
        int t = i / Dd;
        int d = i % Dd;
        int h = d / DK, dk = d % DK;
        float ot = 0.f;
        #pragma unroll
        for (int s = 0; s < Tt; s++) ot += sc[h][t][s] * Vs[s * Dd + d];
        float ol = 0.f;
        #pragma unroll
        for (int m = 0; m < Mm; m++) ol += scl[h][t][m] * mem_v[(h * Mm + m) * DK + dk];
        out[base + i] = ot * wt + ol * wl;
    }
}

// ----------------------------------------------------------------------------
// Residual + LayerNorm: one block per row of 256 elements.
// ----------------------------------------------------------------------------
__global__ __launch_bounds__(256) void ln_kernel(
    const float* __restrict__ fcout, const float* __restrict__ x,
    const float* __restrict__ gamma, const float* __restrict__ beta,
    float* __restrict__ out)
{
    __shared__ float red[8];
    __shared__ float red2[8];
    __shared__ float s_mu, s_rstd;

    const size_t row = blockIdx.x;
    const int tid = threadIdx.x;
    const size_t idx = row * Dd + tid;

    float v = fcout[idx] + x[idx];

    float s = v, s2 = v * v;
    #pragma unroll
    for (int o = 16; o > 0; o >>= 1) {
        s  += __shfl_down_sync(0xffffffffu, s, o);
        s2 += __shfl_down_sync(0xffffffffu, s2, o);
    }
    int warp = tid >> 5, lane = tid & 31;
    if (lane == 0) { red[warp] = s; red2[warp] = s2; }
    __syncthreads();
    if (tid == 0) {
        float ts = 0.f, ts2 = 0.f;
        #pragma unroll
        for (int w = 0; w < 8; w++) { ts += red[w]; ts2 += red2[w]; }
        float mu = ts * (1.f / Dd);
        float var = ts2 * (1.f / Dd) - mu * mu;
        s_mu = mu;
        s_rstd = rsqrtf(var + 1e-5f);
    }
    __syncthreads();

    out[idx] = (v - s_mu) * s_rstd * gamma[tid] + beta[tid];
}

// ----------------------------------------------------------------------------
// Launch
// ----------------------------------------------------------------------------
extern "C" void kernel_launch(void* const* d_in, const int* in_sizes, int n_in,
                              void* d_out, int out_size)
{
    const float* x     = (const float*)d_in[0];
    const float* Wq_w  = (const float*)d_in[1];
    const float* Wq_b  = (const float*)d_in[2];
    const float* Wk_w  = (const float*)d_in[3];
    const float* Wk_b  = (const float*)d_in[4];
    const float* Wv_w  = (const float*)d_in[5];
    const float* Wv_b  = (const float*)d_in[6];
    const float* mem_k = (const float*)d_in[7];
    const float* mem_v = (const float*)d_in[8];
    const float* fc_w  = (const float*)d_in[9];
    const float* fc_b  = (const float*)d_in[10];
    const float* gamma = (const float*)d_in[11];
    const float* beta  = (const float*)d_in[12];
    const float* alpha = (const float*)d_in[13];
    float* out = (float*)d_out;

    float *q, *k, *v, *attn, *fc;
    cudaGetSymbolAddress((void**)&q,    g_q);
    cudaGetSymbolAddress((void**)&k,    g_k);
    cudaGetSymbolAddress((void**)&v,    g_v);
    cudaGetSymbolAddress((void**)&attn, g_attn);
    cudaGetSymbolAddress((void**)&fc,   g_fc);

    dim3 ggrid(ROWS / 64, Dd / 64);
    gemm_bias_kernel<<<ggrid, 256>>>(x, Wq_w, Wq_b, q);
    gemm_bias_kernel<<<ggrid, 256>>>(x, Wk_w, Wk_b, k);
    gemm_bias_kernel<<<ggrid, 256>>>(x, Wv_w, Wv_b, v);

    attn_kernel<<<BN_CNT, 256>>>(q, k, v, mem_k, mem_v, alpha, attn);

    gemm_bias_kernel<<<ggrid, 256>>>(attn, fc_w, fc_b, fc);

    ln_kernel<<<ROWS, 256>>>(fc, x, gamma, beta, out);
}

// round 2
// speedup vs baseline: 2.2116x; 2.2116x over previous
#include <cuda_runtime.h>
#include <math.h>

#define Bb 8
#define Nn 2048
#define Tt 12
#define Dd 256
#define Hh 8
#define DK 32
#define Mm 8
#define ROWS (Bb * Nn * Tt)          // 196608
#define BN_CNT (Bb * Nn)             // 16384
#define SD 260                       // padded smem row stride (floats)

// Scratch (device globals; allocation-free rule)
__device__ float g_q[ROWS * Dd];
__device__ float g_k[ROWS * Dd];
__device__ float g_v[ROWS * Dd];
__device__ float g_attn[ROWS * Dd];
__device__ float g_fc[ROWS * Dd];

__device__ __forceinline__ unsigned f2tf32(float f) {
    unsigned u;
    asm("cvt.rna.tf32.f32 %0, %1;" : "=r"(u) : "f"(f));
    return u;
}

__device__ __forceinline__ void mma_tf32(float* c, const unsigned* a, const unsigned* b) {
    asm volatile(
        "mma.sync.aligned.m16n8k8.row.col.f32.tf32.tf32.f32 "
        "{%0,%1,%2,%3}, {%4,%5,%6,%7}, {%8,%9}, {%0,%1,%2,%3};"
        : "+f"(c[0]), "+f"(c[1]), "+f"(c[2]), "+f"(c[3])
        : "r"(a[0]), "r"(a[1]), "r"(a[2]), "r"(a[3]), "r"(b[0]), "r"(b[1]));
}

// ----------------------------------------------------------------------------
// tf32 tensor-core GEMM: C[m][n] = sum_k A[m][k]*W[n][k] + bias[n]
// BM=BN=128, BK=32. 128 threads = 4 warps (2x2), warp tile 64x64.
// ----------------------------------------------------------------------------
__global__ __launch_bounds__(128) void gemm_tf32_kernel(
    const float* __restrict__ A, const float* __restrict__ W,
    const float* __restrict__ bias, float* __restrict__ C)
{
    __shared__ float As[128][36];
    __shared__ float Bs[128][36];

    const int tid  = threadIdx.x;
    const int lane = tid & 31;
    const int wid  = tid >> 5;
    const int wm   = (wid >> 1) * 64;   // warp m-origin within block
    const int wn   = (wid & 1) * 64;    // warp n-origin within block
    const int m0   = blockIdx.x * 128;
    const int n0   = blockIdx.y * 128;
    const int lr4  = lane >> 2;         // 0..7
    const int lc   = lane & 3;          // 0..3

    float acc[4][8][4];
    #pragma unroll
    for (int i = 0; i < 4; i++)
        #pragma unroll
        for (int j = 0; j < 8; j++)
            #pragma unroll
            for (int r = 0; r < 4; r++) acc[i][j][r] = 0.f;

    for (int k0 = 0; k0 < 256; k0 += 32) {
        // stage A and W tiles (128 rows x 32 k floats each), convert to tf32
        #pragma unroll
        for (int i = 0; i < 8; i++) {
            int idx = i * 128 + tid;        // 0..1023
            int r   = idx >> 3;             // row 0..127
            int c4  = (idx & 7) * 4;        // col 0,4,...,28
            float4 av = *(const float4*)&A[(size_t)(m0 + r) * 256 + k0 + c4];
            float4 bv = *(const float4*)&W[(size_t)(n0 + r) * 256 + k0 + c4];
            float4 at, bt;
            at.x = __uint_as_float(f2tf32(av.x)); at.y = __uint_as_float(f2tf32(av.y));
            at.z = __uint_as_float(f2tf32(av.z)); at.w = __uint_as_float(f2tf32(av.w));
            bt.x = __uint_as_float(f2tf32(bv.x)); bt.y = __uint_as_float(f2tf32(bv.y));
            bt.z = __uint_as_float(f2tf32(bv.z)); bt.w = __uint_as_float(f2tf32(bv.w));
            *(float4*)&As[r][c4] = at;
            *(float4*)&Bs[r][c4] = bt;
        }
        __syncthreads();

        #pragma unroll
        for (int kk = 0; kk < 4; kk++) {
            const int kb = kk * 8;
            unsigned af[4][4];
            unsigned bf[8][2];
            #pragma unroll
            for (int im = 0; im < 4; im++) {
                int r = wm + im * 16 + lr4;
                af[im][0] = __float_as_uint(As[r][kb + lc]);
                af[im][1] = __float_as_uint(As[r + 8][kb + lc]);
                af[im][2] = __float_as_uint(As[r][kb + lc + 4]);
                af[im][3] = __float_as_uint(As[r + 8][kb + lc + 4]);
            }
            #pragma unroll
            for (int in_ = 0; in_ < 8; in_++) {
                int rn = wn + in_ * 8 + lr4;
                bf[in_][0] = __float_as_uint(Bs[rn][kb + lc]);
                bf[in_][1] = __float_as_uint(Bs[rn][kb + lc + 4]);
            }
            #pragma unroll
            for (int im = 0; im < 4; im++)
                #pragma unroll
                for (int in_ = 0; in_ < 8; in_++)
                    mma_tf32(acc[im][in_], af[im], bf[in_]);
        }
        __syncthreads();
    }

    // epilogue: bias add + float2 stores
    #pragma unroll
    for (int im = 0; im < 4; im++) {
        int row = m0 + wm + im * 16 + lr4;
        #pragma unroll
        for (int in_ = 0; in_ < 8; in_++) {
            int col = n0 + wn + in_ * 8 + 2 * lc;
            float b0 = bias[col], b1 = bias[col + 1];
            float2 r0 = make_float2(acc[im][in_][0] + b0, acc[im][in_][1] + b1);
            float2 r1 = make_float2(acc[im][in_][2] + b0, acc[im][in_][3] + b1);
            *(float2*)&C[(size_t)row * 256 + col] = r0;
            *(float2*)&C[(size_t)(row + 8) * 256 + col] = r1;
        }
    }
}

// ----------------------------------------------------------------------------
// Attention: one block per (b, n). float4 everywhere, padded smem rows.
// ----------------------------------------------------------------------------
__global__ __launch_bounds__(256) void attn_kernel(
    const float* __restrict__ Q, const float* __restrict__ K,
    const float* __restrict__ V,
    const float* __restrict__ mem_k, const float* __restrict__ mem_v,
    const float* __restrict__ alpha_l, float* __restrict__ out)
{
    __shared__ float Qs[Tt * SD];
    __shared__ float Ks[Tt * SD];
    __shared__ float Vs[Tt * SD];
    __shared__ float sc[Hh][Tt][Tt];
    __shared__ float scl[Hh][Tt][Mm];

    const int tid = threadIdx.x;
    const size_t base = (size_t)blockIdx.x * (Tt * Dd);

    // stage Q,K,V: 768 float4 each
    for (int i = tid; i < Tt * 64; i += 256) {
        int t = i >> 6, c4 = (i & 63) * 4;
        *(float4*)&Qs[t * SD + c4] = *(const float4*)&Q[base + t * 256 + c4];
        *(float4*)&Ks[t * SD + c4] = *(const float4*)&K[base + t * 256 + c4];
        *(float4*)&Vs[t * SD + c4] = *(const float4*)&V[base + t * 256 + c4];
    }
    __syncthreads();

    const float scale = 0.1767766952966369f;  // 1/sqrt(32)

    // temporal scores (H*T*T = 1152)
    for (int idx = tid; idx < Hh * Tt * Tt; idx += 256) {
        int h = idx / (Tt * Tt);
        int r = idx % (Tt * Tt);
        int t = r / Tt, s = r % Tt;
        float v = -1e30f;
        if (s <= t) {
            const float4* q4 = (const float4*)&Qs[t * SD + h * DK];
            const float4* k4 = (const float4*)&Ks[s * SD + h * DK];
            float acc = 0.f;
            #pragma unroll
            for (int j = 0; j < 8; j++) {
                float4 a = q4[j], b = k4[j];
                acc += a.x * b.x + a.y * b.y + a.z * b.z + a.w * b.w;
            }
            v = acc * scale;
        }
        sc[h][t][s] = v;
    }
    // memory scores (H*T*M = 768)
    for (int idx = tid; idx < Hh * Tt * Mm; idx += 256) {
        int h = idx / (Tt * Mm);
        int r = idx % (Tt * Mm);
        int t = r / Mm, m = r % Mm;
        const float4* q4  = (const float4*)&Qs[t * SD + h * DK];
        const float4* mk4 = (const float4*)&mem_k[(h * Mm + m) * DK];
        float acc = 0.f;
        #pragma unroll
        for (int j = 0; j < 8; j++) {
            float4 a = q4[j], b = mk4[j];
            acc += a.x * b.x + a.y * b.y + a.z * b.z + a.w * b.w;
        }
        scl[h][t][m] = acc * scale;
    }
    __syncthreads();

    // softmax rows
    if (tid < Hh * Tt) {
        int h = tid / Tt, t = tid % Tt;
        float mx = -1e30f;
        for (int s = 0; s <= t; s++) mx = fmaxf(mx, sc[h][t][s]);
        float sum = 0.f;
        for (int s = 0; s <= t; s++) { float e = expf(sc[h][t][s] - mx); sc[h][t][s] = e; sum += e; }
        float inv = 1.f / sum;
        for (int s = 0; s <= t; s++) sc[h][t][s] *= inv;
        for (int s = t + 1; s < Tt; s++) sc[h][t][s] = 0.f;
    } else if (tid < 2 * Hh * Tt) {
        int r = tid - Hh * Tt;
        int h = r / Tt, t = r % Tt;
        float mx = -1e30f;
        #pragma unroll
        for (int m = 0; m < Mm; m++) mx = fmaxf(mx, scl[h][t][m]);
        float sum = 0.f;
        #pragma unroll
        for (int m = 0; m < Mm; m++) { float e = expf(scl[h][t][m] - mx); scl[h][t][m] = e; sum += e; }
        float inv = 1.f / sum;
        #pragma unroll
        for (int m = 0; m < Mm; m++) scl[h][t][m] *= inv;
    }
    __syncthreads();

    const float wl = 1.f / (1.f + expf(-alpha_l[0]));
    const float wt = 1.f - wl;

    // outputs: 768 float4
    for (int i = tid; i < Tt * 64; i += 256) {
        int t = i >> 6, d4 = i & 63;
        int h = d4 >> 3, dk4 = (d4 & 7) * 4;
        float4 ot = make_float4(0.f, 0.f, 0.f, 0.f);
        #pragma unroll
        for (int s = 0; s < Tt; s++) {
            float p = sc[h][t][s];
            float4 v = *(const float4*)&Vs[s * SD + d4 * 4];
            ot.x += p * v.x; ot.y += p * v.y; ot.z += p * v.z; ot.w += p * v.w;
        }
        float4 ol = make_float4(0.f, 0.f, 0.f, 0.f);
        #pragma unroll
        for (int m = 0; m < Mm; m++) {
            float p = scl[h][t][m];
            float4 mv = *(const float4*)&mem_v[(h * Mm + m) * DK + dk4];
            ol.x += p * mv.x; ol.y += p * mv.y; ol.z += p * mv.z; ol.w += p * mv.w;
        }
        float4 o;
        o.x = ot.x * wt + ol.x * wl;
        o.y = ot.y * wt + ol.y * wl;
        o.z = ot.z * wt + ol.z * wl;
        o.w = ot.w * wt + ol.w * wl;
        *(float4*)&out[base + t * 256 + d4 * 4] = o;
    }
}

// ----------------------------------------------------------------------------
// Residual + LayerNorm: one warp per row (256 elems), float4 loads.
// ----------------------------------------------------------------------------
__global__ __launch_bounds__(256) void ln_kernel(
    const float* __restrict__ fcout, const float* __restrict__ x,
    const float* __restrict__ gamma, const float* __restrict__ beta,
    float* __restrict__ out)
{
    const int tid = threadIdx.x;
    const int lane = tid & 31;
    const int wrp = tid >> 5;
    const size_t row = (size_t)blockIdx.x * 8 + wrp;

    const float4* f4 = (const float4*)&fcout[row * 256];
    const float4* x4 = (const float4*)&x[row * 256];
    float4 a0 = f4[lane], a1 = f4[lane + 32];
    float4 b0 = x4[lane], b1 = x4[lane + 32];
    float4 v0 = make_float4(a0.x + b0.x, a0.y + b0.y, a0.z + b0.z, a0.w + b0.w);
    float4 v1 = make_float4(a1.x + b1.x, a1.y + b1.y, a1.z + b1.z, a1.w + b1.w);

    float s  = v0.x + v0.y + v0.z + v0.w + v1.x + v1.y + v1.z + v1.w;
    float s2 = v0.x*v0.x + v0.y*v0.y + v0.z*v0.z + v0.w*v0.w
             + v1.x*v1.x + v1.y*v1.y + v1.z*v1.z + v1.w*v1.w;
    #pragma unroll
    for (int o = 16; o > 0; o >>= 1) {
        s  += __shfl_xor_sync(0xffffffffu, s, o);
        s2 += __shfl_xor_sync(0xffffffffu, s2, o);
    }
    float mu = s * (1.f / 256.f);
    float var = s2 * (1.f / 256.f) - mu * mu;
    float rstd = rsqrtf(var + 1e-5f);

    const float4* g4 = (const float4*)gamma;
    const float4* be4 = (const float4*)beta;
    float4 g0 = g4[lane], g1 = g4[lane + 32];
    float4 e0 = be4[lane], e1 = be4[lane + 32];
    float4 o0, o1;
    o0.x = (v0.x - mu) * rstd * g0.x + e0.x;
    o0.y = (v0.y - mu) * rstd * g0.y + e0.y;
    o0.z = (v0.z - mu) * rstd * g0.z + e0.z;
    o0.w = (v0.w - mu) * rstd * g0.w + e0.w;
    o1.x = (v1.x - mu) * rstd * g1.x + e1.x;
    o1.y = (v1.y - mu) * rstd * g1.y + e1.y;
    o1.z = (v1.z - mu) * rstd * g1.z + e1.z;
    o1.w = (v1.w - mu) * rstd * g1.w + e1.w;
    float4* o4 = (float4*)&out[row * 256];
    o4[lane] = o0;
    o4[lane + 32] = o1;
}

// ----------------------------------------------------------------------------
// Launch
// ----------------------------------------------------------------------------
extern "C" void kernel_launch(void* const* d_in, const int* in_sizes, int n_in,
                              void* d_out, int out_size)
{
    const float* x     = (const float*)d_in[0];
    const float* Wq_w  = (const float*)d_in[1];
    const float* Wq_b  = (const float*)d_in[2];
    const float* Wk_w  = (const float*)d_in[3];
    const float* Wk_b  = (const float*)d_in[4];
    const float* Wv_w  = (const float*)d_in[5];
    const float* Wv_b  = (const float*)d_in[6];
    const float* mem_k = (const float*)d_in[7];
    const float* mem_v = (const float*)d_in[8];
    const float* fc_w  = (const float*)d_in[9];
    const float* fc_b  = (const float*)d_in[10];
    const float* gamma = (const float*)d_in[11];
    const float* beta  = (const float*)d_in[12];
    const float* alpha = (const float*)d_in[13];
    float* out = (float*)d_out;

    float *q, *k, *v, *attn, *fc;
    cudaGetSymbolAddress((void**)&q,    g_q);
    cudaGetSymbolAddress((void**)&k,    g_k);
    cudaGetSymbolAddress((void**)&v,    g_v);
    cudaGetSymbolAddress((void**)&attn, g_attn);
    cudaGetSymbolAddress((void**)&fc,   g_fc);

    dim3 ggrid(ROWS / 128, Dd / 128);
    gemm_tf32_kernel<<<ggrid, 128>>>(x, Wq_w, Wq_b, q);
    gemm_tf32_kernel<<<ggrid, 128>>>(x, Wk_w, Wk_b, k);
    gemm_tf32_kernel<<<ggrid, 128>>>(x, Wv_w, Wv_b, v);

    attn_kernel<<<BN_CNT, 256>>>(q, k, v, mem_k, mem_v, alpha, attn);

    gemm_tf32_kernel<<<ggrid, 128>>>(attn, fc_w, fc_b, fc);

    ln_kernel<<<ROWS / 8, 256>>>(fc, x, gamma, beta, out);
}

// round 3
// speedup vs baseline: 2.4471x; 1.1065x over previous
#include <cuda_runtime.h>
#include <math.h>

#define Bb 8
#define Nn 2048
#define Tt 12
#define Dd 256
#define Hh 8
#define DK 32
#define Mm 8
#define ROWS (Bb * Nn * Tt)          // 196608
#define BN_CNT (Bb * Nn)             // 16384

// Scratch (device globals; allocation-free rule)
__device__ float g_q[ROWS * Dd];
__device__ float g_k[ROWS * Dd];
__device__ float g_v[ROWS * Dd];
__device__ float g_attn[ROWS * Dd];
__device__ float g_fc[ROWS * Dd];

__device__ __forceinline__ unsigned f2tf32(float f) {
    unsigned u;
    asm("cvt.rna.tf32.f32 %0, %1;" : "=r"(u) : "f"(f));
    return u;
}

__device__ __forceinline__ void mma_tf32(float* c, const unsigned* a, const unsigned* b) {
    asm volatile(
        "mma.sync.aligned.m16n8k8.row.col.f32.tf32.tf32.f32 "
        "{%0,%1,%2,%3}, {%4,%5,%6,%7}, {%8,%9}, {%0,%1,%2,%3};"
        : "+f"(c[0]), "+f"(c[1]), "+f"(c[2]), "+f"(c[3])
        : "r"(a[0]), "r"(a[1]), "r"(a[2]), "r"(a[3]), "r"(b[0]), "r"(b[1]));
}

// ----------------------------------------------------------------------------
// tf32 tensor-core GEMM: C[m][n] = sum_k A[m][k]*W[n][k] + bias[n]
// BM=BN=128, BK=32. 128 threads = 4 warps (2x2), warp tile 64x64.
// ----------------------------------------------------------------------------
__global__ __launch_bounds__(128) void gemm_tf32_kernel(
    const float* __restrict__ A, const float* __restrict__ W,
    const float* __restrict__ bias, float* __restrict__ C)
{
    __shared__ float As[128][36];
    __shared__ float Bs[128][36];

    const int tid  = threadIdx.x;
    const int lane = tid & 31;
    const int wid  = tid >> 5;
    const int wm   = (wid >> 1) * 64;   // warp m-origin within block
    const int wn   = (wid & 1) * 64;    // warp n-origin within block
    const int m0   = blockIdx.x * 128;
    const int n0   = blockIdx.y * 128;
    const int lr4  = lane >> 2;         // 0..7
    const int lc   = lane & 3;          // 0..3

    float acc[4][8][4];
    #pragma unroll
    for (int i = 0; i < 4; i++)
        #pragma unroll
        for (int j = 0; j < 8; j++)
            #pragma unroll
            for (int r = 0; r < 4; r++) acc[i][j][r] = 0.f;

    for (int k0 = 0; k0 < 256; k0 += 32) {
        #pragma unroll
        for (int i = 0; i < 8; i++) {
            int idx = i * 128 + tid;        // 0..1023
            int r   = idx >> 3;             // row 0..127
            int c4  = (idx & 7) * 4;        // col 0,4,...,28
            float4 av = *(const float4*)&A[(size_t)(m0 + r) * 256 + k0 + c4];
            float4 bv = *(const float4*)&W[(size_t)(n0 + r) * 256 + k0 + c4];
            float4 at, bt;
            at.x = __uint_as_float(f2tf32(av.x)); at.y = __uint_as_float(f2tf32(av.y));
            at.z = __uint_as_float(f2tf32(av.z)); at.w = __uint_as_float(f2tf32(av.w));
            bt.x = __uint_as_float(f2tf32(bv.x)); bt.y = __uint_as_float(f2tf32(bv.y));
            bt.z = __uint_as_float(f2tf32(bv.z)); bt.w = __uint_as_float(f2tf32(bv.w));
            *(float4*)&As[r][c4] = at;
            *(float4*)&Bs[r][c4] = bt;
        }
        __syncthreads();

        #pragma unroll
        for (int kk = 0; kk < 4; kk++) {
            const int kb = kk * 8;
            unsigned af[4][4];
            unsigned bf[8][2];
            #pragma unroll
            for (int im = 0; im < 4; im++) {
                int r = wm + im * 16 + lr4;
                af[im][0] = __float_as_uint(As[r][kb + lc]);
                af[im][1] = __float_as_uint(As[r + 8][kb + lc]);
                af[im][2] = __float_as_uint(As[r][kb + lc + 4]);
                af[im][3] = __float_as_uint(As[r + 8][kb + lc + 4]);
            }
            #pragma unroll
            for (int in_ = 0; in_ < 8; in_++) {
                int rn = wn + in_ * 8 + lr4;
                bf[in_][0] = __float_as_uint(Bs[rn][kb + lc]);
                bf[in_][1] = __float_as_uint(Bs[rn][kb + lc + 4]);
            }
            #pragma unroll
            for (int im = 0; im < 4; im++)
                #pragma unroll
                for (int in_ = 0; in_ < 8; in_++)
                    mma_tf32(acc[im][in_], af[im], bf[in_]);
        }
        __syncthreads();
    }

    #pragma unroll
    for (int im = 0; im < 4; im++) {
        int row = m0 + wm + im * 16 + lr4;
        #pragma unroll
        for (int in_ = 0; in_ < 8; in_++) {
            int col = n0 + wn + in_ * 8 + 2 * lc;
            float b0 = bias[col], b1 = bias[col + 1];
            float2 r0 = make_float2(acc[im][in_][0] + b0, acc[im][in_][1] + b1);
            float2 r1 = make_float2(acc[im][in_][2] + b0, acc[im][in_][3] + b1);
            *(float2*)&C[(size_t)row * 256 + col] = r0;
            *(float2*)&C[(size_t)(row + 8) * 256 + col] = r1;
        }
    }
}

// ----------------------------------------------------------------------------
// Attention v2: one WARP per (bn, head). lane = dk channel. Zero shared mem.
// Scores via shfl-butterfly reductions; softmax distributed row-per-lane;
// probability broadcast via static shfl; everything else in registers.
// ----------------------------------------------------------------------------
__global__ __launch_bounds__(256) void attn_kernel(
    const float* __restrict__ Q, const float* __restrict__ K,
    const float* __restrict__ V,
    const float* __restrict__ mem_k, const float* __restrict__ mem_v,
    const float* __restrict__ alpha_l, float* __restrict__ out)
{
    const int lane = threadIdx.x & 31;
    const int h    = threadIdx.x >> 5;          // 0..7 : head
    const size_t base = (size_t)blockIdx.x * (Tt * Dd) + h * DK + lane;

    // register-resident Q, K, V columns (lane = dk)
    float q[Tt], k[Tt], v[Tt];
    #pragma unroll
    for (int t = 0; t < Tt; t++) {
        q[t] = Q[base + t * Dd];
        k[t] = K[base + t * Dd];
        v[t] = V[base + t * Dd];
    }
    float mk[Mm], mv[Mm];
    #pragma unroll
    for (int m = 0; m < Mm; m++) {
        mk[m] = mem_k[(h * Mm + m) * DK + lane];
        mv[m] = mem_v[(h * Mm + m) * DK + lane];
    }

    const float scale = 0.1767766952966369f;    // 1/sqrt(32)

    float trow[Tt];   // lane t owns time-probability row t
    float mrow[Mm];   // lane 16+t owns memory-probability row t
    #pragma unroll
    for (int s = 0; s < Tt; s++) trow[s] = 0.f;
    #pragma unroll
    for (int m = 0; m < Mm; m++) mrow[m] = 0.f;

    // ---- scores ----
    #pragma unroll
    for (int t = 0; t < Tt; t++) {
        float p[Tt];
        #pragma unroll
        for (int s = 0; s < Tt; s++)
            if (s <= t) p[s] = q[t] * k[s];
        #pragma unroll
        for (int off = 16; off > 0; off >>= 1)
            #pragma unroll
            for (int s = 0; s < Tt; s++)
                if (s <= t) p[s] += __shfl_xor_sync(0xffffffffu, p[s], off);

        float pm[Mm];
        #pragma unroll
        for (int m = 0; m < Mm; m++) pm[m] = q[t] * mk[m];
        #pragma unroll
        for (int off = 16; off > 0; off >>= 1)
            #pragma unroll
            for (int m = 0; m < Mm; m++)
                pm[m] += __shfl_xor_sync(0xffffffffu, pm[m], off);

        if (lane == t) {
            #pragma unroll
            for (int s = 0; s < Tt; s++)
                trow[s] = (s <= t) ? p[s] * scale : -1e30f;
        }
        if (lane == 16 + t) {
            #pragma unroll
            for (int m = 0; m < Mm; m++) mrow[m] = pm[m] * scale;
        }
    }

    // ---- softmax (row-per-lane, no divergence; non-owner lanes compute junk) ----
    {
        float mx = -1e30f;
        #pragma unroll
        for (int s = 0; s < Tt; s++) mx = fmaxf(mx, trow[s]);
        float sum = 0.f;
        #pragma unroll
        for (int s = 0; s < Tt; s++) { float e = __expf(trow[s] - mx); trow[s] = e; sum += e; }
        float inv = 1.f / sum;
        #pragma unroll
        for (int s = 0; s < Tt; s++) trow[s] *= inv;
    }
    {
        float mx = -1e30f;
        #pragma unroll
        for (int m = 0; m < Mm; m++) mx = fmaxf(mx, mrow[m]);
        float sum = 0.f;
        #pragma unroll
        for (int m = 0; m < Mm; m++) { float e = __expf(mrow[m] - mx); mrow[m] = e; sum += e; }
        float inv = 1.f / sum;
        #pragma unroll
        for (int m = 0; m < Mm; m++) mrow[m] *= inv;
    }

    const float wl = 1.f / (1.f + __expf(-alpha_l[0]));
    const float wt = 1.f - wl;

    // ---- outputs: broadcast probs from owner lanes, FMA against register V ----
    #pragma unroll
    for (int t = 0; t < Tt; t++) {
        float ot = 0.f;
        #pragma unroll
        for (int s = 0; s < Tt; s++)
            if (s <= t) {
                float pp = __shfl_sync(0xffffffffu, trow[s], t);
                ot += pp * v[s];
            }
        float ol = 0.f;
        #pragma unroll
        for (int m = 0; m < Mm; m++) {
            float pl = __shfl_sync(0xffffffffu, mrow[m], 16 + t);
            ol += pl * mv[m];
        }
        out[base + t * Dd] = ot * wt + ol * wl;
    }
}

// ----------------------------------------------------------------------------
// Residual + LayerNorm: one warp per row (256 elems), float4 loads.
// ----------------------------------------------------------------------------
__global__ __launch_bounds__(256) void ln_kernel(
    const float* __restrict__ fcout, const float* __restrict__ x,
    const float* __restrict__ gamma, const float* __restrict__ beta,
    float* __restrict__ out)
{
    const int tid = threadIdx.x;
    const int lane = tid & 31;
    const int wrp = tid >> 5;
    const size_t row = (size_t)blockIdx.x * 8 + wrp;

    const float4* f4 = (const float4*)&fcout[row * 256];
    const float4* x4 = (const float4*)&x[row * 256];
    float4 a0 = f4[lane], a1 = f4[lane + 32];
    float4 b0 = x4[lane], b1 = x4[lane + 32];
    float4 v0 = make_float4(a0.x + b0.x, a0.y + b0.y, a0.z + b0.z, a0.w + b0.w);
    float4 v1 = make_float4(a1.x + b1.x, a1.y + b1.y, a1.z + b1.z, a1.w + b1.w);

    float s  = v0.x + v0.y + v0.z + v0.w + v1.x + v1.y + v1.z + v1.w;
    float s2 = v0.x*v0.x + v0.y*v0.y + v0.z*v0.z + v0.w*v0.w
             + v1.x*v1.x + v1.y*v1.y + v1.z*v1.z + v1.w*v1.w;
    #pragma unroll
    for (int o = 16; o > 0; o >>= 1) {
        s  += __shfl_xor_sync(0xffffffffu, s, o);
        s2 += __shfl_xor_sync(0xffffffffu, s2, o);
    }
    float mu = s * (1.f / 256.f);
    float var = s2 * (1.f / 256.f) - mu * mu;
    float rstd = rsqrtf(var + 1e-5f);

    const float4* g4 = (const float4*)gamma;
    const float4* be4 = (const float4*)beta;
    float4 g0 = g4[lane], g1 = g4[lane + 32];
    float4 e0 = be4[lane], e1 = be4[lane + 32];
    float4 o0, o1;
    o0.x = (v0.x - mu) * rstd * g0.x + e0.x;
    o0.y = (v0.y - mu) * rstd * g0.y + e0.y;
    o0.z = (v0.z - mu) * rstd * g0.z + e0.z;
    o0.w = (v0.w - mu) * rstd * g0.w + e0.w;
    o1.x = (v1.x - mu) * rstd * g1.x + e1.x;
    o1.y = (v1.y - mu) * rstd * g1.y + e1.y;
    o1.z = (v1.z - mu) * rstd * g1.z + e1.z;
    o1.w = (v1.w - mu) * rstd * g1.w + e1.w;
    float4* o4 = (float4*)&out[row * 256];
    o4[lane] = o0;
    o4[lane + 32] = o1;
}

// ----------------------------------------------------------------------------
// Launch
// ----------------------------------------------------------------------------
extern "C" void kernel_launch(void* const* d_in, const int* in_sizes, int n_in,
                              void* d_out, int out_size)
{
    const float* x     = (const float*)d_in[0];
    const float* Wq_w  = (const float*)d_in[1];
    const float* Wq_b  = (const float*)d_in[2];
    const float* Wk_w  = (const float*)d_in[3];
    const float* Wk_b  = (const float*)d_in[4];
    const float* Wv_w  = (const float*)d_in[5];
    const float* Wv_b  = (const float*)d_in[6];
    const float* mem_k = (const float*)d_in[7];
    const float* mem_v = (const float*)d_in[8];
    const float* fc_w  = (const float*)d_in[9];
    const float* fc_b  = (const float*)d_in[10];
    const float* gamma = (const float*)d_in[11];
    const float* beta  = (const float*)d_in[12];
    const float* alpha = (const float*)d_in[13];
    float* out = (float*)d_out;

    float *q, *k, *v, *attn, *fc;
    cudaGetSymbolAddress((void**)&q,    g_q);
    cudaGetSymbolAddress((void**)&k,    g_k);
    cudaGetSymbolAddress((void**)&v,    g_v);
    cudaGetSymbolAddress((void**)&attn, g_attn);
    cudaGetSymbolAddress((void**)&fc,   g_fc);

    dim3 ggrid(ROWS / 128, Dd / 128);
    gemm_tf32_kernel<<<ggrid, 128>>>(x, Wq_w, Wq_b, q);
    gemm_tf32_kernel<<<ggrid, 128>>>(x, Wk_w, Wk_b, k);
    gemm_tf32_kernel<<<ggrid, 128>>>(x, Wv_w, Wv_b, v);

    attn_kernel<<<BN_CNT, 256>>>(q, k, v, mem_k, mem_v, alpha, attn);

    gemm_tf32_kernel<<<ggrid, 128>>>(attn, fc_w, fc_b, fc);

    ln_kernel<<<ROWS / 8, 256>>>(fc, x, gamma, beta, out);
}

// round 5
// speedup vs baseline: 3.5662x; 1.4573x over previous
#include <cuda_runtime.h>
#include <cuda_bf16.h>
#include <math.h>

#define Bb 8
#define Nn 2048
#define Tt 12
#define Dd 256
#define Hh 8
#define DK 32
#define Mm 8
#define ROWS (Bb * Nn * Tt)          // 196608
#define BN_CNT (Bb * Nn)             // 16384

// Scratch (device globals; allocation-free rule)
__device__ float g_q[ROWS * Dd];
__device__ float g_k[ROWS * Dd];
__device__ float g_v[ROWS * Dd];
__device__ float g_attn[ROWS * Dd];
__device__ float g_fc[ROWS * Dd];

__device__ __forceinline__ unsigned f2tf32(float f) {
    unsigned u;
    asm("cvt.rna.tf32.f32 %0, %1;" : "=r"(u) : "f"(f));
    return u;
}

__device__ __forceinline__ void mma_tf32(float* c, const unsigned* a, const unsigned* b) {
    asm volatile(
        "mma.sync.aligned.m16n8k8.row.col.f32.tf32.tf32.f32 "
        "{%0,%1,%2,%3}, {%4,%5,%6,%7}, {%8,%9}, {%0,%1,%2,%3};"
        : "+f"(c[0]), "+f"(c[1]), "+f"(c[2]), "+f"(c[3])
        : "r"(a[0]), "r"(a[1]), "r"(a[2]), "r"(a[3]), "r"(b[0]), "r"(b[1]));
}

__device__ __forceinline__ void mma_bf16(float* c, const unsigned* a, const unsigned* b) {
    asm volatile(
        "mma.sync.aligned.m16n8k16.row.col.f32.bf16.bf16.f32 "
        "{%0,%1,%2,%3}, {%4,%5,%6,%7}, {%8,%9}, {%0,%1,%2,%3};"
        : "+f"(c[0]), "+f"(c[1]), "+f"(c[2]), "+f"(c[3])
        : "r"(a[0]), "r"(a[1]), "r"(a[2]), "r"(a[3]), "r"(b[0]), "r"(b[1]));
}

// ----------------------------------------------------------------------------
// bf16 tensor-core GEMM: C[m][n] = sum_k A[m][k]*W[n][k] + bias[n]
// BM=BN=128, BK=32, 128 threads = 4 warps (2x2), warp tile 64x64, mma m16n8k16.
// ----------------------------------------------------------------------------
__global__ __launch_bounds__(128) void gemm_bf16_kernel(
    const float* __restrict__ A, const float* __restrict__ W,
    const float* __restrict__ bias, float* __restrict__ C)
{
    __shared__ __nv_bfloat16 As[128][40];
    __shared__ __nv_bfloat16 Bs[128][40];

    const int tid  = threadIdx.x;
    const int lane = tid & 31;
    const int wid  = tid >> 5;
    const int wm   = (wid >> 1) * 64;
    const int wn   = (wid & 1) * 64;
    const int m0   = blockIdx.x * 128;
    const int n0   = blockIdx.y * 128;
    const int g    = lane >> 2;   // 0..7
    const int c    = lane & 3;    // 0..3

    float acc[4][8][4];
    #pragma unroll
    for (int i = 0; i < 4; i++)
        #pragma unroll
        for (int j = 0; j < 8; j++)
            #pragma unroll
            for (int r = 0; r < 4; r++) acc[i][j][r] = 0.f;

    for (int k0 = 0; k0 < 256; k0 += 32) {
        #pragma unroll
        for (int i = 0; i < 8; i++) {
            int idx = i * 128 + tid;        // 0..1023
            int r   = idx >> 3;             // row 0..127
            int c4  = (idx & 7) * 4;        // col 0,4,...,28
            float4 av = *(const float4*)&A[(size_t)(m0 + r) * 256 + k0 + c4];
            float4 bv = *(const float4*)&W[(size_t)(n0 + r) * 256 + k0 + c4];
            __nv_bfloat162 a0, a1, b0, b1;
            a0.x = __float2bfloat16_rn(av.x); a0.y = __float2bfloat16_rn(av.y);
            a1.x = __float2bfloat16_rn(av.z); a1.y = __float2bfloat16_rn(av.w);
            b0.x = __float2bfloat16_rn(bv.x); b0.y = __float2bfloat16_rn(bv.y);
            b1.x = __float2bfloat16_rn(bv.z); b1.y = __float2bfloat16_rn(bv.w);
            *(__nv_bfloat162*)&As[r][c4]     = a0;
            *(__nv_bfloat162*)&As[r][c4 + 2] = a1;
            *(__nv_bfloat162*)&Bs[r][c4]     = b0;
            *(__nv_bfloat162*)&Bs[r][c4 + 2] = b1;
        }
        __syncthreads();

        #pragma unroll
        for (int kk = 0; kk < 2; kk++) {
            const int kb = kk * 16;
            unsigned af[4][4];
            unsigned bf[8][2];
            #pragma unroll
            for (int im = 0; im < 4; im++) {
                int r = wm + im * 16 + g;
                af[im][0] = *(const unsigned*)&As[r][kb + 2 * c];
                af[im][1] = *(const unsigned*)&As[r + 8][kb + 2 * c];
                af[im][2] = *(const unsigned*)&As[r][kb + 2 * c + 8];
                af[im][3] = *(const unsigned*)&As[r + 8][kb + 2 * c + 8];
            }
            #pragma unroll
            for (int in_ = 0; in_ < 8; in_++) {
                int rn = wn + in_ * 8 + g;
                bf[in_][0] = *(const unsigned*)&Bs[rn][kb + 2 * c];
                bf[in_][1] = *(const unsigned*)&Bs[rn][kb + 2 * c + 8];
            }
            #pragma unroll
            for (int im = 0; im < 4; im++)
                #pragma unroll
                for (int in_ = 0; in_ < 8; in_++)
                    mma_bf16(acc[im][in_], af[im], bf[in_]);
        }
        __syncthreads();
    }

    #pragma unroll
    for (int im = 0; im < 4; im++) {
        int row = m0 + wm + im * 16 + g;
        #pragma unroll
        for (int in_ = 0; in_ < 8; in_++) {
            int col = n0 + wn + in_ * 8 + 2 * c;
            float b0 = bias[col], b1 = bias[col + 1];
            float2 r0 = make_float2(acc[im][in_][0] + b0, acc[im][in_][1] + b1);
            float2 r1 = make_float2(acc[im][in_][2] + b0, acc[im][in_][3] + b1);
            *(float2*)&C[(size_t)row * 256 + col] = r0;
            *(float2*)&C[(size_t)(row + 8) * 256 + col] = r1;
        }
    }
}

// ----------------------------------------------------------------------------
// Attention v3 (fixed): tensor-core per-warp. Block = one bn (8 warps = 8 heads).
// ----------------------------------------------------------------------------
#define QS_STRIDE 264
#define PS_STRIDE 28

__global__ __launch_bounds__(256) void attn_kernel(
    const float* __restrict__ Q, const float* __restrict__ K,
    const float* __restrict__ V,
    const float* __restrict__ mem_k, const float* __restrict__ mem_v,
    const float* __restrict__ alpha_l, float* __restrict__ out)
{
    __shared__ float Qs[Tt * QS_STRIDE];
    __shared__ float Ks[Tt * QS_STRIDE];
    __shared__ float Vs[Tt * QS_STRIDE];
    __shared__ float Ps[Hh][Tt * PS_STRIDE];

    const int tid  = threadIdx.x;
    const int lane = tid & 31;
    const int h    = tid >> 5;        // head
    const int g    = lane >> 2;       // 0..7
    const int c    = lane & 3;        // 0..3
    const int hc   = h * DK;
    const size_t base = (size_t)blockIdx.x * (Tt * Dd);

    // stage Q,K,V (12x256 each), tf32-converted
    for (int i = tid; i < Tt * 64; i += 256) {
        int r = i >> 6, c4 = (i & 63) * 4;
        float4 qv = *(const float4*)&Q[base + r * 256 + c4];
        float4 kv = *(const float4*)&K[base + r * 256 + c4];
        float4 vv = *(const float4*)&V[base + r * 256 + c4];
        float4 qt, kt, vt;
        qt.x = __uint_as_float(f2tf32(qv.x)); qt.y = __uint_as_float(f2tf32(qv.y));
        qt.z = __uint_as_float(f2tf32(qv.z)); qt.w = __uint_as_float(f2tf32(qv.w));
        kt.x = __uint_as_float(f2tf32(kv.x)); kt.y = __uint_as_float(f2tf32(kv.y));
        kt.z = __uint_as_float(f2tf32(kv.z)); kt.w = __uint_as_float(f2tf32(kv.w));
        vt.x = __uint_as_float(f2tf32(vv.x)); vt.y = __uint_as_float(f2tf32(vv.y));
        vt.z = __uint_as_float(f2tf32(vv.z)); vt.w = __uint_as_float(f2tf32(vv.w));
        *(float4*)&Qs[r * QS_STRIDE + c4] = qt;
        *(float4*)&Ks[r * QS_STRIDE + c4] = kt;
        *(float4*)&Vs[r * QS_STRIDE + c4] = vt;
    }
    __syncthreads();

    // ---- scores: S (12x16 over 2 n-tiles), Sm (12x8) ----
    float s0[4] = {0.f, 0.f, 0.f, 0.f};
    float s1[4] = {0.f, 0.f, 0.f, 0.f};
    float sm[4] = {0.f, 0.f, 0.f, 0.f};
    #pragma unroll
    for (int kk = 0; kk < 4; kk++) {
        const int kb = hc + kk * 8;
        unsigned a[4];
        a[0] = __float_as_uint(Qs[g * QS_STRIDE + kb + c]);
        a[1] = (g < 4) ? __float_as_uint(Qs[(g + 8) * QS_STRIDE + kb + c]) : 0u;
        a[2] = __float_as_uint(Qs[g * QS_STRIDE + kb + c + 4]);
        a[3] = (g < 4) ? __float_as_uint(Qs[(g + 8) * QS_STRIDE + kb + c + 4]) : 0u;
        unsigned b0[2], b1[2], bm[2];
        b0[0] = __float_as_uint(Ks[g * QS_STRIDE + kb + c]);
        b0[1] = __float_as_uint(Ks[g * QS_STRIDE + kb + c + 4]);
        b1[0] = (g < 4) ? __float_as_uint(Ks[(g + 8) * QS_STRIDE + kb + c]) : 0u;
        b1[1] = (g < 4) ? __float_as_uint(Ks[(g + 8) * QS_STRIDE + kb + c + 4]) : 0u;
        // FIXED: f2tf32 already returns the bit pattern — use directly.
        bm[0] = f2tf32(__ldg(&mem_k[(h * Mm + g) * DK + kk * 8 + c]));
        bm[1] = f2tf32(__ldg(&mem_k[(h * Mm + g) * DK + kk * 8 + c + 4]));
        mma_tf32(s0, a, b0);
        mma_tf32(s1, a, b1);
        mma_tf32(sm, a, bm);
    }

    // ---- causal mask + scale ----
    const float scale = 0.1767766952966369f;
    const int s00 = 2 * c, s01 = 2 * c + 1, s10 = 8 + 2 * c, s11 = 8 + 2 * c + 1;
    const int tlo = g, thi = g + 8;
    float e[8];
    e[0] = (s00 <= tlo) ? s0[0] * scale : -1e30f;
    e[1] = (s01 <= tlo) ? s0[1] * scale : -1e30f;
    e[2] = (s10 <= tlo) ? s1[0] * scale : -1e30f;
    e[3] = (s11 <= tlo) ? s1[1] * scale : -1e30f;
    e[4] = (s00 <= thi) ? s0[2] * scale : -1e30f;
    e[5] = (s01 <= thi) ? s0[3] * scale : -1e30f;
    e[6] = (s10 <= thi) ? s1[2] * scale : -1e30f;
    e[7] = (s11 <= thi) ? s1[3] * scale : -1e30f;

    // ---- softmax over s (row in one quad: 2-step shfl) ----
    float mlo = fmaxf(fmaxf(e[0], e[1]), fmaxf(e[2], e[3]));
    float mhi = fmaxf(fmaxf(e[4], e[5]), fmaxf(e[6], e[7]));
    mlo = fmaxf(mlo, __shfl_xor_sync(0xffffffffu, mlo, 1));
    mlo = fmaxf(mlo, __shfl_xor_sync(0xffffffffu, mlo, 2));
    mhi = fmaxf(mhi, __shfl_xor_sync(0xffffffffu, mhi, 1));
    mhi = fmaxf(mhi, __shfl_xor_sync(0xffffffffu, mhi, 2));
    #pragma unroll
    for (int j = 0; j < 4; j++) e[j] = __expf(e[j] - mlo);
    #pragma unroll
    for (int j = 4; j < 8; j++) e[j] = __expf(e[j] - mhi);
    float slo = e[0] + e[1] + e[2] + e[3];
    float shi = e[4] + e[5] + e[6] + e[7];
    slo += __shfl_xor_sync(0xffffffffu, slo, 1);
    slo += __shfl_xor_sync(0xffffffffu, slo, 2);
    shi += __shfl_xor_sync(0xffffffffu, shi, 1);
    shi += __shfl_xor_sync(0xffffffffu, shi, 2);
    float rlo = 1.f / slo, rhi = 1.f / shi;
    #pragma unroll
    for (int j = 0; j < 4; j++) e[j] *= rlo;
    #pragma unroll
    for (int j = 4; j < 8; j++) e[j] *= rhi;

    // ---- memory softmax (no mask) ----
    float em[4];
    em[0] = sm[0] * scale; em[1] = sm[1] * scale;
    em[2] = sm[2] * scale; em[3] = sm[3] * scale;
    float mmlo = fmaxf(em[0], em[1]);
    float mmhi = fmaxf(em[2], em[3]);
    mmlo = fmaxf(mmlo, __shfl_xor_sync(0xffffffffu, mmlo, 1));
    mmlo = fmaxf(mmlo, __shfl_xor_sync(0xffffffffu, mmlo, 2));
    mmhi = fmaxf(mmhi, __shfl_xor_sync(0xffffffffu, mmhi, 1));
    mmhi = fmaxf(mmhi, __shfl_xor_sync(0xffffffffu, mmhi, 2));
    em[0] = __expf(em[0] - mmlo); em[1] = __expf(em[1] - mmlo);
    em[2] = __expf(em[2] - mmhi); em[3] = __expf(em[3] - mmhi);
    float smlo = em[0] + em[1];
    float smhi = em[2] + em[3];
    smlo += __shfl_xor_sync(0xffffffffu, smlo, 1);
    smlo += __shfl_xor_sync(0xffffffffu, smlo, 2);
    smhi += __shfl_xor_sync(0xffffffffu, smhi, 1);
    smhi += __shfl_xor_sync(0xffffffffu, smhi, 2);
    em[0] *= 1.f / smlo; em[1] *= 1.f / smlo;
    em[2] *= 1.f / smhi; em[3] *= 1.f / smhi;

    // ---- stage P (tf32) to per-warp smem ----
    float* Pw = Ps[h];
    Pw[tlo * PS_STRIDE + s00] = __uint_as_float(f2tf32(e[0]));
    Pw[tlo * PS_STRIDE + s01] = __uint_as_float(f2tf32(e[1]));
    Pw[tlo * PS_STRIDE + s10] = __uint_as_float(f2tf32(e[2]));
    Pw[tlo * PS_STRIDE + s11] = __uint_as_float(f2tf32(e[3]));
    Pw[tlo * PS_STRIDE + 16 + s00] = __uint_as_float(f2tf32(em[0]));
    Pw[tlo * PS_STRIDE + 16 + s01] = __uint_as_float(f2tf32(em[1]));
    if (g < 4) {
        Pw[thi * PS_STRIDE + s00] = __uint_as_float(f2tf32(e[4]));
        Pw[thi * PS_STRIDE + s01] = __uint_as_float(f2tf32(e[5]));
        Pw[thi * PS_STRIDE + s10] = __uint_as_float(f2tf32(e[6]));
        Pw[thi * PS_STRIDE + s11] = __uint_as_float(f2tf32(e[7]));
        Pw[thi * PS_STRIDE + 16 + s00] = __uint_as_float(f2tf32(em[2]));
        Pw[thi * PS_STRIDE + 16 + s01] = __uint_as_float(f2tf32(em[3]));
    }
    __syncwarp();

    // ---- O = P V (k=16 over 2 ksteps) + Pm mem_v (k=8) ----
    float o[4][4], l[4][4];
    #pragma unroll
    for (int nt = 0; nt < 4; nt++)
        #pragma unroll
        for (int r = 0; r < 4; r++) { o[nt][r] = 0.f; l[nt][r] = 0.f; }

    #pragma unroll
    for (int kk = 0; kk < 2; kk++) {
        unsigned pa[4];
        pa[0] = __float_as_uint(Pw[g * PS_STRIDE + kk * 8 + c]);
        pa[1] = (g < 4) ? __float_as_uint(Pw[(g + 8) * PS_STRIDE + kk * 8 + c]) : 0u;
        pa[2] = __float_as_uint(Pw[g * PS_STRIDE + kk * 8 + c + 4]);
        pa[3] = (g < 4) ? __float_as_uint(Pw[(g + 8) * PS_STRIDE + kk * 8 + c + 4]) : 0u;
        const int k0i = kk * 8 + c;
        const int k1i = kk * 8 + c + 4;
        #pragma unroll
        for (int nt = 0; nt < 4; nt++) {
            unsigned vb[2];
            vb[0] = __float_as_uint(Vs[k0i * QS_STRIDE + hc + nt * 8 + g]);
            vb[1] = (k1i < Tt) ? __float_as_uint(Vs[k1i * QS_STRIDE + hc + nt * 8 + g]) : 0u;
            mma_tf32(o[nt], pa, vb);
        }
    }
    {
        unsigned pa[4];
        pa[0] = __float_as_uint(Pw[g * PS_STRIDE + 16 + c]);
        pa[1] = (g < 4) ? __float_as_uint(Pw[(g + 8) * PS_STRIDE + 16 + c]) : 0u;
        pa[2] = __float_as_uint(Pw[g * PS_STRIDE + 16 + c + 4]);
        pa[3] = (g < 4) ? __float_as_uint(Pw[(g + 8) * PS_STRIDE + 16 + c + 4]) : 0u;
        #pragma unroll
        for (int nt = 0; nt < 4; nt++) {
            unsigned mb[2];
            // FIXED: use f2tf32 result directly (it is already the bit pattern).
            mb[0] = f2tf32(__ldg(&mem_v[(h * Mm + c) * DK + nt * 8 + g]));
            mb[1] = f2tf32(__ldg(&mem_v[(h * Mm + c + 4) * DK + nt * 8 + g]));
            mma_tf32(l[nt], pa, mb);
        }
    }

    // ---- gated fusion + store ----
    const float wl = 1.f / (1.f + __expf(-alpha_l[0]));
    const float wt = 1.f - wl;
    #pragma unroll
    for (int nt = 0; nt < 4; nt++) {
        int col = hc + nt * 8 + 2 * c;
        float2 r0 = make_float2(wt * o[nt][0] + wl * l[nt][0],
                                wt * o[nt][1] + wl * l[nt][1]);
        *(float2*)&out[base + tlo * 256 + col] = r0;
        if (g < 4) {
            float2 r1 = make_float2(wt * o[nt][2] + wl * l[nt][2],
                                    wt * o[nt][3] + wl * l[nt][3]);
            *(float2*)&out[base + thi * 256 + col] = r1;
        }
    }
}

// ----------------------------------------------------------------------------
// Residual + LayerNorm: one warp per row (256 elems), float4 loads.
// ----------------------------------------------------------------------------
__global__ __launch_bounds__(256) void ln_kernel(
    const float* __restrict__ fcout, const float* __restrict__ x,
    const float* __restrict__ gamma, const float* __restrict__ beta,
    float* __restrict__ out)
{
    const int tid = threadIdx.x;
    const int lane = tid & 31;
    const int wrp = tid >> 5;
    const size_t row = (size_t)blockIdx.x * 8 + wrp;

    const float4* f4 = (const float4*)&fcout[row * 256];
    const float4* x4 = (const float4*)&x[row * 256];
    float4 a0 = f4[lane], a1 = f4[lane + 32];
    float4 b0 = x4[lane], b1 = x4[lane + 32];
    float4 v0 = make_float4(a0.x + b0.x, a0.y + b0.y, a0.z + b0.z, a0.w + b0.w);
    float4 v1 = make_float4(a1.x + b1.x, a1.y + b1.y, a1.z + b1.z, a1.w + b1.w);

    float s  = v0.x + v0.y + v0.z + v0.w + v1.x + v1.y + v1.z + v1.w;
    float s2 = v0.x*v0.x + v0.y*v0.y + v0.z*v0.z + v0.w*v0.w
             + v1.x*v1.x + v1.y*v1.y + v1.z*v1.z + v1.w*v1.w;
    #pragma unroll
    for (int o = 16; o > 0; o >>= 1) {
        s  += __shfl_xor_sync(0xffffffffu, s, o);
        s2 += __shfl_xor_sync(0xffffffffu, s2, o);
    }
    float mu = s * (1.f / 256.f);
    float var = s2 * (1.f / 256.f) - mu * mu;
    float rstd = rsqrtf(var + 1e-5f);

    const float4* g4 = (const float4*)gamma;
    const float4* be4 = (const float4*)beta;
    float4 g0 = g4[lane], g1 = g4[lane + 32];
    float4 e0 = be4[lane], e1 = be4[lane + 32];
    float4 o0, o1;
    o0.x = (v0.x - mu) * rstd * g0.x + e0.x;
    o0.y = (v0.y - mu) * rstd * g0.y + e0.y;
    o0.z = (v0.z - mu) * rstd * g0.z + e0.z;
    o0.w = (v0.w - mu) * rstd * g0.w + e0.w;
    o1.x = (v1.x - mu) * rstd * g1.x + e1.x;
    o1.y = (v1.y - mu) * rstd * g1.y + e1.y;
    o1.z = (v1.z - mu) * rstd * g1.z + e1.z;
    o1.w = (v1.w - mu) * rstd * g1.w + e1.w;
    float4* o4 = (float4*)&out[row * 256];
    o4[lane] = o0;
    o4[lane + 32] = o1;
}

// ----------------------------------------------------------------------------
// Launch
// ----------------------------------------------------------------------------
extern "C" void kernel_launch(void* const* d_in, const int* in_sizes, int n_in,
                              void* d_out, int out_size)
{
    const float* x     = (const float*)d_in[0];
    const float* Wq_w  = (const float*)d_in[1];
    const float* Wq_b  = (const float*)d_in[2];
    const float* Wk_w  = (const float*)d_in[3];
    const float* Wk_b  = (const float*)d_in[4];
    const float* Wv_w  = (const float*)d_in[5];
    const float* Wv_b  = (const float*)d_in[6];
    const float* mem_k = (const float*)d_in[7];
    const float* mem_v = (const float*)d_in[8];
    const float* fc_w  = (const float*)d_in[9];
    const float* fc_b  = (const float*)d_in[10];
    const float* gamma = (const float*)d_in[11];
    const float* beta  = (const float*)d_in[12];
    const float* alpha = (const float*)d_in[13];
    float* out = (float*)d_out;

    float *q, *k, *v, *attn, *fc;
    cudaGetSymbolAddress((void**)&q,    g_q);
    cudaGetSymbolAddress((void**)&k,    g_k);
    cudaGetSymbolAddress((void**)&v,    g_v);
    cudaGetSymbolAddress((void**)&attn, g_attn);
    cudaGetSymbolAddress((void**)&fc,   g_fc);

    dim3 ggrid(ROWS / 128, Dd / 128);
    gemm_bf16_kernel<<<ggrid, 128>>>(x, Wq_w, Wq_b, q);
    gemm_bf16_kernel<<<ggrid, 128>>>(x, Wk_w, Wk_b, k);
    gemm_bf16_kernel<<<ggrid, 128>>>(x, Wv_w, Wv_b, v);

    attn_kernel<<<BN_CNT, 256>>>(q, k, v, mem_k, mem_v, alpha, attn);

    gemm_bf16_kernel<<<ggrid, 128>>>(attn, fc_w, fc_b, fc);

    ln_kernel<<<ROWS / 8, 256>>>(fc, x, gamma, beta, out);
}

// round 6
// speedup vs baseline: 4.4786x; 1.2558x over previous
#include <cuda_runtime.h>
#include <cuda_bf16.h>
#include <math.h>

#define Bb 8
#define Nn 2048
#define Tt 12
#define Dd 256
#define Hh 8
#define DK 32
#define Mm 8
#define ROWS (Bb * Nn * Tt)          // 196608
#define BN_CNT (Bb * Nn)             // 16384

// Scratch (device globals; allocation-free rule)
__device__ __nv_bfloat16 g_xb[ROWS * Dd];
__device__ __nv_bfloat16 g_qb[ROWS * Dd];
__device__ __nv_bfloat16 g_kb[ROWS * Dd];
__device__ __nv_bfloat16 g_vb[ROWS * Dd];
__device__ __nv_bfloat16 g_ab[ROWS * Dd];
__device__ float g_fc[ROWS * Dd];
__device__ __nv_bfloat16 g_wq[Dd * Dd];
__device__ __nv_bfloat16 g_wk[Dd * Dd];
__device__ __nv_bfloat16 g_wv[Dd * Dd];
__device__ __nv_bfloat16 g_wf[Dd * Dd];

#define CP_ASYNC16(dst, src) \
    asm volatile("cp.async.cg.shared.global [%0], [%1], 16;" :: "r"(dst), "l"(src))
#define CP_COMMIT() asm volatile("cp.async.commit_group;")
#define CP_WAIT(n)  asm volatile("cp.async.wait_group %0;" :: "n"(n))

__device__ __forceinline__ unsigned f2tf32(float f) {
    unsigned u;
    asm("cvt.rna.tf32.f32 %0, %1;" : "=r"(u) : "f"(f));
    return u;
}

__device__ __forceinline__ void mma_tf32(float* c, const unsigned* a, const unsigned* b) {
    asm volatile(
        "mma.sync.aligned.m16n8k8.row.col.f32.tf32.tf32.f32 "
        "{%0,%1,%2,%3}, {%4,%5,%6,%7}, {%8,%9}, {%0,%1,%2,%3};"
        : "+f"(c[0]), "+f"(c[1]), "+f"(c[2]), "+f"(c[3])
        : "r"(a[0]), "r"(a[1]), "r"(a[2]), "r"(a[3]), "r"(b[0]), "r"(b[1]));
}

__device__ __forceinline__ void mma_bf16(float* c, const unsigned* a, const unsigned* b) {
    asm volatile(
        "mma.sync.aligned.m16n8k16.row.col.f32.bf16.bf16.f32 "
        "{%0,%1,%2,%3}, {%4,%5,%6,%7}, {%8,%9}, {%0,%1,%2,%3};"
        : "+f"(c[0]), "+f"(c[1]), "+f"(c[2]), "+f"(c[3])
        : "r"(a[0]), "r"(a[1]), "r"(a[2]), "r"(a[3]), "r"(b[0]), "r"(b[1]));
}

// ----------------------------------------------------------------------------
// fp32 -> bf16 conversion (float4 granularity)
// ----------------------------------------------------------------------------
__global__ __launch_bounds__(256) void cvt_kernel(
    const float* __restrict__ in, __nv_bfloat16* __restrict__ out, int n4)
{
    int i = blockIdx.x * 256 + threadIdx.x;
    if (i < n4) {
        float4 v = ((const float4*)in)[i];
        __nv_bfloat162 a = __float22bfloat162_rn(make_float2(v.x, v.y));
        __nv_bfloat162 b = __float22bfloat162_rn(make_float2(v.z, v.w));
        ((__nv_bfloat162*)out)[2 * i]     = a;
        ((__nv_bfloat162*)out)[2 * i + 1] = b;
    }
}

// ----------------------------------------------------------------------------
// bf16-in GEMM v2: C[m][n] = sum_k A[m][k]*W[n][k] + bias[n]
// BM=BN=128, BK=32, 256 threads (8 warps, warp tile 64x32),
// 2-stage cp.async double buffer; output bf16 (Cb) or fp32 (Cf).
// ----------------------------------------------------------------------------
__global__ __launch_bounds__(256) void gemm_v2_kernel(
    const __nv_bfloat16* __restrict__ A, const __nv_bfloat16* __restrict__ W,
    const float* __restrict__ bias,
    __nv_bfloat16* __restrict__ Cb, float* __restrict__ Cf)
{
    __shared__ __nv_bfloat16 As[2][128][40];   // 32 used + 8 pad (80B rows)
    __shared__ __nv_bfloat16 Bs[2][128][40];

    const int tid  = threadIdx.x;
    const int lane = tid & 31;
    const int wid  = tid >> 5;
    const int wm   = (wid >> 2) * 64;   // 0 or 64
    const int wn   = (wid & 3) * 32;    // 0,32,64,96
    const int m0   = blockIdx.x * 128;
    const int n0   = blockIdx.y * 128;
    const int g    = lane >> 2;   // 0..7
    const int c    = lane & 3;    // 0..3

    float acc[4][4][4];
    #pragma unroll
    for (int i = 0; i < 4; i++)
        #pragma unroll
        for (int j = 0; j < 4; j++)
            #pragma unroll
            for (int r = 0; r < 4; r++) acc[i][j][r] = 0.f;

    // per-thread load map: 2 chunks of 16B (8 halfs) for A and for B per stage
    const int idx0 = tid * 2;
    const int r0   = idx0 >> 2;
    const int h0   = (idx0 & 3) << 3;
    const int idx1 = tid * 2 + 1;
    const int r1   = idx1 >> 2;
    const int h1   = (idx1 & 3) << 3;

    auto load_tile = [&](int st, int k0) {
        CP_ASYNC16((unsigned)__cvta_generic_to_shared(&As[st][r0][h0]),
                   &A[(size_t)(m0 + r0) * 256 + k0 + h0]);
        CP_ASYNC16((unsigned)__cvta_generic_to_shared(&Bs[st][r0][h0]),
                   &W[(size_t)(n0 + r0) * 256 + k0 + h0]);
        CP_ASYNC16((unsigned)__cvta_generic_to_shared(&As[st][r1][h1]),
                   &A[(size_t)(m0 + r1) * 256 + k0 + h1]);
        CP_ASYNC16((unsigned)__cvta_generic_to_shared(&Bs[st][r1][h1]),
                   &W[(size_t)(n0 + r1) * 256 + k0 + h1]);
    };

    load_tile(0, 0);  CP_COMMIT();
    load_tile(1, 32); CP_COMMIT();

    #pragma unroll
    for (int kt = 0; kt < 8; kt++) {
        const int st = kt & 1;
        if (kt == 7) { CP_WAIT(0); } else { CP_WAIT(1); }
        __syncthreads();

        #pragma unroll
        for (int kk = 0; kk < 2; kk++) {
            const int kb = kk * 16;
            unsigned af[4][4];
            unsigned bf[4][2];
            #pragma unroll
            for (int im = 0; im < 4; im++) {
                int r = wm + im * 16 + g;
                af[im][0] = *(const unsigned*)&As[st][r][kb + 2 * c];
                af[im][1] = *(const unsigned*)&As[st][r + 8][kb + 2 * c];
                af[im][2] = *(const unsigned*)&As[st][r][kb + 2 * c + 8];
                af[im][3] = *(const unsigned*)&As[st][r + 8][kb + 2 * c + 8];
            }
            #pragma unroll
            for (int in_ = 0; in_ < 4; in_++) {
                int rn = wn + in_ * 8 + g;
                bf[in_][0] = *(const unsigned*)&Bs[st][rn][kb + 2 * c];
                bf[in_][1] = *(const unsigned*)&Bs[st][rn][kb + 2 * c + 8];
            }
            #pragma unroll
            for (int im = 0; im < 4; im++)
                #pragma unroll
                for (int in_ = 0; in_ < 4; in_++)
                    mma_bf16(acc[im][in_], af[im], bf[in_]);
        }
        __syncthreads();
        if (kt + 2 < 8) { load_tile(st, (kt + 2) * 32); CP_COMMIT(); }
    }

    #pragma unroll
    for (int im = 0; im < 4; im++) {
        int row = m0 + wm + im * 16 + g;
        #pragma unroll
        for (int in_ = 0; in_ < 4; in_++) {
            int col = n0 + wn + in_ * 8 + 2 * c;
            float b0 = bias[col], b1 = bias[col + 1];
            float v00 = acc[im][in_][0] + b0, v01 = acc[im][in_][1] + b1;
            float v10 = acc[im][in_][2] + b0, v11 = acc[im][in_][3] + b1;
            if (Cf) {
                *(float2*)&Cf[(size_t)row * 256 + col]       = make_float2(v00, v01);
                *(float2*)&Cf[(size_t)(row + 8) * 256 + col] = make_float2(v10, v11);
            } else {
                *(__nv_bfloat162*)&Cb[(size_t)row * 256 + col] =
                    __float22bfloat162_rn(make_float2(v00, v01));
                *(__nv_bfloat162*)&Cb[(size_t)(row + 8) * 256 + col] =
                    __float22bfloat162_rn(make_float2(v10, v11));
            }
        }
    }
}

// ----------------------------------------------------------------------------
// Attention v4: tensor-core per-warp, bf16 in / bf16 out.
// ----------------------------------------------------------------------------
#define QS_STRIDE 264
#define PS_STRIDE 28

__global__ __launch_bounds__(256) void attn_kernel(
    const __nv_bfloat16* __restrict__ Q, const __nv_bfloat16* __restrict__ K,
    const __nv_bfloat16* __restrict__ V,
    const float* __restrict__ mem_k, const float* __restrict__ mem_v,
    const float* __restrict__ alpha_l, __nv_bfloat16* __restrict__ out)
{
    __shared__ float Qs[Tt * QS_STRIDE];
    __shared__ float Ks[Tt * QS_STRIDE];
    __shared__ float Vs[Tt * QS_STRIDE];
    __shared__ float Ps[Hh][Tt * PS_STRIDE];

    const int tid  = threadIdx.x;
    const int lane = tid & 31;
    const int h    = tid >> 5;        // head
    const int g    = lane >> 2;       // 0..7
    const int c    = lane & 3;        // 0..3
    const int hc   = h * DK;
    const size_t base = (size_t)blockIdx.x * (Tt * Dd);

    // stage Q,K,V (12x256 bf16 each) -> fp32 smem (bf16 values exact in tf32)
    for (int i = tid; i < Tt * 32; i += 256) {
        int r = i >> 5, c8 = (i & 31) * 8;
        uint4 qu = *(const uint4*)&Q[base + r * 256 + c8];
        uint4 ku = *(const uint4*)&K[base + r * 256 + c8];
        uint4 vu = *(const uint4*)&V[base + r * 256 + c8];
        const __nv_bfloat162* qp = (const __nv_bfloat162*)&qu;
        const __nv_bfloat162* kp = (const __nv_bfloat162*)&ku;
        const __nv_bfloat162* vp = (const __nv_bfloat162*)&vu;
        #pragma unroll
        for (int j = 0; j < 4; j++) {
            float2 qf = __bfloat1622float2(qp[j]);
            float2 kf = __bfloat1622float2(kp[j]);
            float2 vf = __bfloat1622float2(vp[j]);
            *(float2*)&Qs[r * QS_STRIDE + c8 + 2 * j] = qf;
            *(float2*)&Ks[r * QS_STRIDE + c8 + 2 * j] = kf;
            *(float2*)&Vs[r * QS_STRIDE + c8 + 2 * j] = vf;
        }
    }
    __syncthreads();

    // ---- scores: S (12x16 over 2 n-tiles), Sm (12x8) ----
    float s0[4] = {0.f, 0.f, 0.f, 0.f};
    float s1[4] = {0.f, 0.f, 0.f, 0.f};
    float sm[4] = {0.f, 0.f, 0.f, 0.f};
    #pragma unroll
    for (int kk = 0; kk < 4; kk++) {
        const int kb = hc + kk * 8;
        unsigned a[4];
        a[0] = __float_as_uint(Qs[g * QS_STRIDE + kb + c]);
        a[1] = (g < 4) ? __float_as_uint(Qs[(g + 8) * QS_STRIDE + kb + c]) : 0u;
        a[2] = __float_as_uint(Qs[g * QS_STRIDE + kb + c + 4]);
        a[3] = (g < 4) ? __float_as_uint(Qs[(g + 8) * QS_STRIDE + kb + c + 4]) : 0u;
        unsigned b0[2], b1[2], bm[2];
        b0[0] = __float_as_uint(Ks[g * QS_STRIDE + kb + c]);
        b0[1] = __float_as_uint(Ks[g * QS_STRIDE + kb + c + 4]);
        b1[0] = (g < 4) ? __float_as_uint(Ks[(g + 8) * QS_STRIDE + kb + c]) : 0u;
        b1[1] = (g < 4) ? __float_as_uint(Ks[(g + 8) * QS_STRIDE + kb + c + 4]) : 0u;
        bm[0] = f2tf32(__ldg(&mem_k[(h * Mm + g) * DK + kk * 8 + c]));
        bm[1] = f2tf32(__ldg(&mem_k[(h * Mm + g) * DK + kk * 8 + c + 4]));
        mma_tf32(s0, a, b0);
        mma_tf32(s1, a, b1);
        mma_tf32(sm, a, bm);
    }

    // ---- causal mask + scale ----
    const float scale = 0.1767766952966369f;
    const int s00 = 2 * c, s01 = 2 * c + 1, s10 = 8 + 2 * c, s11 = 8 + 2 * c + 1;
    const int tlo = g, thi = g + 8;
    float e[8];
    e[0] = (s00 <= tlo) ? s0[0] * scale : -1e30f;
    e[1] = (s01 <= tlo) ? s0[1] * scale : -1e30f;
    e[2] = (s10 <= tlo) ? s1[0] * scale : -1e30f;
    e[3] = (s11 <= tlo) ? s1[1] * scale : -1e30f;
    e[4] = (s00 <= thi) ? s0[2] * scale : -1e30f;
    e[5] = (s01 <= thi) ? s0[3] * scale : -1e30f;
    e[6] = (s10 <= thi) ? s1[2] * scale : -1e30f;
    e[7] = (s11 <= thi) ? s1[3] * scale : -1e30f;

    // ---- softmax over s (row in one quad: 2-step shfl) ----
    float mlo = fmaxf(fmaxf(e[0], e[1]), fmaxf(e[2], e[3]));
    float mhi = fmaxf(fmaxf(e[4], e[5]), fmaxf(e[6], e[7]));
    mlo = fmaxf(mlo, __shfl_xor_sync(0xffffffffu, mlo, 1));
    mlo = fmaxf(mlo, __shfl_xor_sync(0xffffffffu, mlo, 2));
    mhi = fmaxf(mhi, __shfl_xor_sync(0xffffffffu, mhi, 1));
    mhi = fmaxf(mhi, __shfl_xor_sync(0xffffffffu, mhi, 2));
    #pragma unroll
    for (int j = 0; j < 4; j++) e[j] = __expf(e[j] - mlo);
    #pragma unroll
    for (int j = 4; j < 8; j++) e[j] = __expf(e[j] - mhi);
    float slo = e[0] + e[1] + e[2] + e[3];
    float shi = e[4] + e[5] + e[6] + e[7];
    slo += __shfl_xor_sync(0xffffffffu, slo, 1);
    slo += __shfl_xor_sync(0xffffffffu, slo, 2);
    shi += __shfl_xor_sync(0xffffffffu, shi, 1);
    shi += __shfl_xor_sync(0xffffffffu, shi, 2);
    float rlo = 1.f / slo, rhi = 1.f / shi;
    #pragma unroll
    for (int j = 0; j < 4; j++) e[j] *= rlo;
    #pragma unroll
    for (int j = 4; j < 8; j++) e[j] *= rhi;

    // ---- memory softmax (no mask) ----
    float em[4];
    em[0] = sm[0] * scale; em[1] = sm[1] * scale;
    em[2] = sm[2] * scale; em[3] = sm[3] * scale;
    float mmlo = fmaxf(em[0], em[1]);
    float mmhi = fmaxf(em[2], em[3]);
    mmlo = fmaxf(mmlo, __shfl_xor_sync(0xffffffffu, mmlo, 1));
    mmlo = fmaxf(mmlo, __shfl_xor_sync(0xffffffffu, mmlo, 2));
    mmhi = fmaxf(mmhi, __shfl_xor_sync(0xffffffffu, mmhi, 1));
    mmhi = fmaxf(mmhi, __shfl_xor_sync(0xffffffffu, mmhi, 2));
    em[0] = __expf(em[0] - mmlo); em[1] = __expf(em[1] - mmlo);
    em[2] = __expf(em[2] - mmhi); em[3] = __expf(em[3] - mmhi);
    float smlo = em[0] + em[1];
    float smhi = em[2] + em[3];
    smlo += __shfl_xor_sync(0xffffffffu, smlo, 1);
    smlo += __shfl_xor_sync(0xffffffffu, smlo, 2);
    smhi += __shfl_xor_sync(0xffffffffu, smhi, 1);
    smhi += __shfl_xor_sync(0xffffffffu, smhi, 2);
    em[0] *= 1.f / smlo; em[1] *= 1.f / smlo;
    em[2] *= 1.f / smhi; em[3] *= 1.f / smhi;

    // ---- stage P (tf32) to per-warp smem ----
    float* Pw = Ps[h];
    Pw[tlo * PS_STRIDE + s00] = __uint_as_float(f2tf32(e[0]));
    Pw[tlo * PS_STRIDE + s01] = __uint_as_float(f2tf32(e[1]));
    Pw[tlo * PS_STRIDE + s10] = __uint_as_float(f2tf32(e[2]));
    Pw[tlo * PS_STRIDE + s11] = __uint_as_float(f2tf32(e[3]));
    Pw[tlo * PS_STRIDE + 16 + s00] = __uint_as_float(f2tf32(em[0]));
    Pw[tlo * PS_STRIDE + 16 + s01] = __uint_as_float(f2tf32(em[1]));
    if (g < 4) {
        Pw[thi * PS_STRIDE + s00] = __uint_as_float(f2tf32(e[4]));
        Pw[thi * PS_STRIDE + s01] = __uint_as_float(f2tf32(e[5]));
        Pw[thi * PS_STRIDE + s10] = __uint_as_float(f2tf32(e[6]));
        Pw[thi * PS_STRIDE + s11] = __uint_as_float(f2tf32(e[7]));
        Pw[thi * PS_STRIDE + 16 + s00] = __uint_as_float(f2tf32(em[2]));
        Pw[thi * PS_STRIDE + 16 + s01] = __uint_as_float(f2tf32(em[3]));
    }
    __syncwarp();

    // ---- O = P V (k=16 over 2 ksteps) + Pm mem_v (k=8) ----
    float o[4][4], l[4][4];
    #pragma unroll
    for (int nt = 0; nt < 4; nt++)
        #pragma unroll
        for (int r = 0; r < 4; r++) { o[nt][r] = 0.f; l[nt][r] = 0.f; }

    #pragma unroll
    for (int kk = 0; kk < 2; kk++) {
        unsigned pa[4];
        pa[0] = __float_as_uint(Pw[g * PS_STRIDE + kk * 8 + c]);
        pa[1] = (g < 4) ? __float_as_uint(Pw[(g + 8) * PS_STRIDE + kk * 8 + c]) : 0u;
        pa[2] = __float_as_uint(Pw[g * PS_STRIDE + kk * 8 + c + 4]);
        pa[3] = (g < 4) ? __float_as_uint(Pw[(g + 8) * PS_STRIDE + kk * 8 + c + 4]) : 0u;
        const int k0i = kk * 8 + c;
        const int k1i = kk * 8 + c + 4;
        #pragma unroll
        for (int nt = 0; nt < 4; nt++) {
            unsigned vb[2];
            vb[0] = __float_as_uint(Vs[k0i * QS_STRIDE + hc + nt * 8 + g]);
            vb[1] = (k1i < Tt) ? __float_as_uint(Vs[k1i * QS_STRIDE + hc + nt * 8 + g]) : 0u;
            mma_tf32(o[nt], pa, vb);
        }
    }
    {
        unsigned pa[4];
        pa[0] = __float_as_uint(Pw[g * PS_STRIDE + 16 + c]);
        pa[1] = (g < 4) ? __float_as_uint(Pw[(g + 8) * PS_STRIDE + 16 + c]) : 0u;
        pa[2] = __float_as_uint(Pw[g * PS_STRIDE + 16 + c + 4]);
        pa[3] = (g < 4) ? __float_as_uint(Pw[(g + 8) * PS_STRIDE + 16 + c + 4]) : 0u;
        #pragma unroll
        for (int nt = 0; nt < 4; nt++) {
            unsigned mb[2];
            mb[0] = f2tf32(__ldg(&mem_v[(h * Mm + c) * DK + nt * 8 + g]));
            mb[1] = f2tf32(__ldg(&mem_v[(h * Mm + c + 4) * DK + nt * 8 + g]));
            mma_tf32(l[nt], pa, mb);
        }
    }

    // ---- gated fusion + bf16 store ----
    const float wl = 1.f / (1.f + __expf(-alpha_l[0]));
    const float wt = 1.f - wl;
    #pragma unroll
    for (int nt = 0; nt < 4; nt++) {
        int col = hc + nt * 8 + 2 * c;
        *(__nv_bfloat162*)&out[base + tlo * 256 + col] = __float22bfloat162_rn(
            make_float2(wt * o[nt][0] + wl * l[nt][0], wt * o[nt][1] + wl * l[nt][1]));
        if (g < 4) {
            *(__nv_bfloat162*)&out[base + thi * 256 + col] = __float22bfloat162_rn(
                make_float2(wt * o[nt][2] + wl * l[nt][2], wt * o[nt][3] + wl * l[nt][3]));
        }
    }
}

// ----------------------------------------------------------------------------
// Residual + LayerNorm: one warp per row (256 elems), float4 loads.
// ----------------------------------------------------------------------------
__global__ __launch_bounds__(256) void ln_kernel(
    const float* __restrict__ fcout, const float* __restrict__ x,
    const float* __restrict__ gamma, const float* __restrict__ beta,
    float* __restrict__ out)
{
    const int tid = threadIdx.x;
    const int lane = tid & 31;
    const int wrp = tid >> 5;
    const size_t row = (size_t)blockIdx.x * 8 + wrp;

    const float4* f4 = (const float4*)&fcout[row * 256];
    const float4* x4 = (const float4*)&x[row * 256];
    float4 a0 = f4[lane], a1 = f4[lane + 32];
    float4 b0 = x4[lane], b1 = x4[lane + 32];
    float4 v0 = make_float4(a0.x + b0.x, a0.y + b0.y, a0.z + b0.z, a0.w + b0.w);
    float4 v1 = make_float4(a1.x + b1.x, a1.y + b1.y, a1.z + b1.z, a1.w + b1.w);

    float s  = v0.x + v0.y + v0.z + v0.w + v1.x + v1.y + v1.z + v1.w;
    float s2 = v0.x*v0.x + v0.y*v0.y + v0.z*v0.z + v0.w*v0.w
             + v1.x*v1.x + v1.y*v1.y + v1.z*v1.z + v1.w*v1.w;
    #pragma unroll
    for (int o = 16; o > 0; o >>= 1) {
        s  += __shfl_xor_sync(0xffffffffu, s, o);
        s2 += __shfl_xor_sync(0xffffffffu, s2, o);
    }
    float mu = s * (1.f / 256.f);
    float var = s2 * (1.f / 256.f) - mu * mu;
    float rstd = rsqrtf(var + 1e-5f);

    const float4* g4 = (const float4*)gamma;
    const float4* be4 = (const float4*)beta;
    float4 g0 = g4[lane], g1 = g4[lane + 32];
    float4 e0 = be4[lane], e1 = be4[lane + 32];
    float4 o0, o1;
    o0.x = (v0.x - mu) * rstd * g0.x + e0.x;
    o0.y = (v0.y - mu) * rstd * g0.y + e0.y;
    o0.z = (v0.z - mu) * rstd * g0.z + e0.z;
    o0.w = (v0.w - mu) * rstd * g0.w + e0.w;
    o1.x = (v1.x - mu) * rstd * g1.x + e1.x;
    o1.y = (v1.y - mu) * rstd * g1.y + e1.y;
    o1.z = (v1.z - mu) * rstd * g1.z + e1.z;
    o1.w = (v1.w - mu) * rstd * g1.w + e1.w;
    float4* o4 = (float4*)&out[row * 256];
    o4[lane] = o0;
    o4[lane + 32] = o1;
}

// ----------------------------------------------------------------------------
// Launch
// ----------------------------------------------------------------------------
extern "C" void kernel_launch(void* const* d_in, const int* in_sizes, int n_in,
                              void* d_out, int out_size)
{
    const float* x     = (const float*)d_in[0];
    const float* Wq_w  = (const float*)d_in[1];
    const float* Wq_b  = (const float*)d_in[2];
    const float* Wk_w  = (const float*)d_in[3];
    const float* Wk_b  = (const float*)d_in[4];
    const float* Wv_w  = (const float*)d_in[5];
    const float* Wv_b  = (const float*)d_in[6];
    const float* mem_k = (const float*)d_in[7];
    const float* mem_v = (const float*)d_in[8];
    const float* fc_w  = (const float*)d_in[9];
    const float* fc_b  = (const float*)d_in[10];
    const float* gamma = (const float*)d_in[11];
    const float* beta  = (const float*)d_in[12];
    const float* alpha = (const float*)d_in[13];
    float* out = (float*)d_out;

    __nv_bfloat16 *xb, *qb, *kb, *vb, *ab, *wq, *wk, *wv, *wf;
    float* fc;
    cudaGetSymbolAddress((void**)&xb, g_xb);
    cudaGetSymbolAddress((void**)&qb, g_qb);
    cudaGetSymbolAddress((void**)&kb, g_kb);
    cudaGetSymbolAddress((void**)&vb, g_vb);
    cudaGetSymbolAddress((void**)&ab, g_ab);
    cudaGetSymbolAddress((void**)&fc, g_fc);
    cudaGetSymbolAddress((void**)&wq, g_wq);
    cudaGetSymbolAddress((void**)&wk, g_wk);
    cudaGetSymbolAddress((void**)&wv, g_wv);
    cudaGetSymbolAddress((void**)&wf, g_wf);

    // conversions
    const int xn4 = ROWS * Dd / 4;      // 12582912
    const int wn4 = Dd * Dd / 4;        // 16384
    cvt_kernel<<<(xn4 + 255) / 256, 256>>>(x, xb, xn4);
    cvt_kernel<<<(wn4 + 255) / 256, 256>>>(Wq_w, wq, wn4);
    cvt_kernel<<<(wn4 + 255) / 256, 256>>>(Wk_w, wk, wn4);
    cvt_kernel<<<(wn4 + 255) / 256, 256>>>(Wv_w, wv, wn4);
    cvt_kernel<<<(wn4 + 255) / 256, 256>>>(fc_w, wf, wn4);

    dim3 ggrid(ROWS / 128, Dd / 128);
    gemm_v2_kernel<<<ggrid, 256>>>(xb, wq, Wq_b, qb, nullptr);
    gemm_v2_kernel<<<ggrid, 256>>>(xb, wk, Wk_b, kb, nullptr);
    gemm_v2_kernel<<<ggrid, 256>>>(xb, wv, Wv_b, vb, nullptr);

    attn_kernel<<<BN_CNT, 256>>>(qb, kb, vb, mem_k, mem_v, alpha, ab);

    gemm_v2_kernel<<<ggrid, 256>>>(ab, wf, fc_b, nullptr, fc);

    ln_kernel<<<ROWS / 8, 256>>>(fc, x, gamma, beta, out);
}

// round 7
// speedup vs baseline: 5.1000x; 1.1387x over previous
#include <cuda_runtime.h>
#include <cuda_bf16.h>
#include <math.h>

#define Bb 8
#define Nn 2048
#define Tt 12
#define Dd 256
#define Hh 8
#define DK 32
#define Mm 8
#define ROWS (Bb * Nn * Tt)          // 196608
#define BN_CNT (Bb * Nn)             // 16384

// Scratch (device globals; allocation-free rule)
__device__ __nv_bfloat16 g_xb[ROWS * Dd];
__device__ __nv_bfloat16 g_qb[ROWS * Dd];
__device__ __nv_bfloat16 g_kb[ROWS * Dd];
__device__ __nv_bfloat16 g_vb[ROWS * Dd];
__device__ __nv_bfloat16 g_ab[ROWS * Dd];
__device__ float g_fc[ROWS * Dd];
__device__ __nv_bfloat16 g_wq[Dd * Dd];
__device__ __nv_bfloat16 g_wk[Dd * Dd];
__device__ __nv_bfloat16 g_wv[Dd * Dd];
__device__ __nv_bfloat16 g_wf[Dd * Dd];

#define CP_ASYNC16(dst, src) \
    asm volatile("cp.async.cg.shared.global [%0], [%1], 16;" :: "r"(dst), "l"(src))
#define CP_COMMIT() asm volatile("cp.async.commit_group;")
#define CP_WAIT(n)  asm volatile("cp.async.wait_group %0;" :: "n"(n))

#define LDSM_X4(r0, r1, r2, r3, addr) \
    asm volatile("ldmatrix.sync.aligned.m8n8.x4.shared.b16 {%0,%1,%2,%3}, [%4];" \
        : "=r"(r0), "=r"(r1), "=r"(r2), "=r"(r3) : "r"(addr))

__device__ __forceinline__ unsigned f2tf32(float f) {
    unsigned u;
    asm("cvt.rna.tf32.f32 %0, %1;" : "=r"(u) : "f"(f));
    return u;
}

__device__ __forceinline__ void mma_tf32(float* c, const unsigned* a, const unsigned* b) {
    asm volatile(
        "mma.sync.aligned.m16n8k8.row.col.f32.tf32.tf32.f32 "
        "{%0,%1,%2,%3}, {%4,%5,%6,%7}, {%8,%9}, {%0,%1,%2,%3};"
        : "+f"(c[0]), "+f"(c[1]), "+f"(c[2]), "+f"(c[3])
        : "r"(a[0]), "r"(a[1]), "r"(a[2]), "r"(a[3]), "r"(b[0]), "r"(b[1]));
}

__device__ __forceinline__ void mma_bf16(float* c, const unsigned* a, const unsigned* b) {
    asm volatile(
        "mma.sync.aligned.m16n8k16.row.col.f32.bf16.bf16.f32 "
        "{%0,%1,%2,%3}, {%4,%5,%6,%7}, {%8,%9}, {%0,%1,%2,%3};"
        : "+f"(c[0]), "+f"(c[1]), "+f"(c[2]), "+f"(c[3])
        : "r"(a[0]), "r"(a[1]), "r"(a[2]), "r"(a[3]), "r"(b[0]), "r"(b[1]));
}

// ----------------------------------------------------------------------------
// fp32 -> bf16 conversion (float4 granularity)
// ----------------------------------------------------------------------------
__global__ __launch_bounds__(256) void cvt_kernel(
    const float* __restrict__ in, __nv_bfloat16* __restrict__ out, int n4)
{
    int i = blockIdx.x * 256 + threadIdx.x;
    if (i < n4) {
        float4 v = ((const float4*)in)[i];
        __nv_bfloat162 a = __float22bfloat162_rn(make_float2(v.x, v.y));
        __nv_bfloat162 b = __float22bfloat162_rn(make_float2(v.z, v.w));
        ((__nv_bfloat162*)out)[2 * i]     = a;
        ((__nv_bfloat162*)out)[2 * i + 1] = b;
    }
}

// ----------------------------------------------------------------------------
// GEMM core v3: C[m][n] = sum_k A[m][k]*W[n][k] + bias[n]
// BM=BN=128, BK=32, 256 threads (8 warps, warp tile 64x32),
// 2-stage cp.async double buffer, ldmatrix.x4 fragment loads.
// ----------------------------------------------------------------------------
__device__ __forceinline__ void gemm_core(
    const __nv_bfloat16* __restrict__ A, const __nv_bfloat16* __restrict__ W,
    const float* __restrict__ bias,
    __nv_bfloat16* __restrict__ Cb, float* __restrict__ Cf, int m0, int n0)
{
    __shared__ __nv_bfloat16 As[2][128][40];   // 32 used + 8 pad (80B rows)
    __shared__ __nv_bfloat16 Bs[2][128][40];

    const int tid  = threadIdx.x;
    const int lane = tid & 31;
    const int wid  = tid >> 5;
    const int wm   = (wid >> 2) * 64;   // 0 or 64
    const int wn   = (wid & 3) * 32;    // 0,32,64,96
    const int g    = lane >> 2;   // 0..7
    const int c    = lane & 3;    // 0..3

    float acc[4][4][4];
    #pragma unroll
    for (int i = 0; i < 4; i++)
        #pragma unroll
        for (int j = 0; j < 4; j++)
            #pragma unroll
            for (int r = 0; r < 4; r++) acc[i][j][r] = 0.f;

    // per-thread load map: 2 chunks of 16B (8 halfs) for A and B per stage
    const int idx0 = tid * 2;
    const int r0   = idx0 >> 2;
    const int h0   = (idx0 & 3) << 3;
    const int idx1 = idx0 + 1;
    const int r1   = idx1 >> 2;
    const int h1   = (idx1 & 3) << 3;

    const unsigned sA = (unsigned)__cvta_generic_to_shared(&As[0][0][0]);
    const unsigned sB = (unsigned)__cvta_generic_to_shared(&Bs[0][0][0]);
    const unsigned STG = 128 * 40 * 2;  // bytes per stage

    auto load_tile = [&](int st, int k0) {
        CP_ASYNC16(sA + st * STG + (r0 * 40 + h0) * 2, &A[(size_t)(m0 + r0) * 256 + k0 + h0]);
        CP_ASYNC16(sB + st * STG + (r0 * 40 + h0) * 2, &W[(size_t)(n0 + r0) * 256 + k0 + h0]);
        CP_ASYNC16(sA + st * STG + (r1 * 40 + h1) * 2, &A[(size_t)(m0 + r1) * 256 + k0 + h1]);
        CP_ASYNC16(sB + st * STG + (r1 * 40 + h1) * 2, &W[(size_t)(n0 + r1) * 256 + k0 + h1]);
    };

    // ldmatrix per-lane row/col offsets
    const int arow = lane & 15;                 // A: matrices {rows0-7,rows8-15}@kb, then @kb+8
    const int acol = (lane >> 4) << 3;          //    lanes 16-31 -> +8 cols
    const int brow = (lane & 7) + ((lane >> 4) << 3);  // B: n-tile pair rows
    const int bcol = ((lane >> 3) & 1) << 3;           //    alternate kb / kb+8

    load_tile(0, 0);  CP_COMMIT();
    load_tile(1, 32); CP_COMMIT();

    #pragma unroll
    for (int kt = 0; kt < 8; kt++) {
        const int st = kt & 1;
        if (kt == 7) { CP_WAIT(0); } else { CP_WAIT(1); }
        __syncthreads();

        #pragma unroll
        for (int kk = 0; kk < 2; kk++) {
            const int kb = kk * 16;
            unsigned af[4][4];
            unsigned bf[4][2];
            #pragma unroll
            for (int im = 0; im < 4; im++) {
                unsigned addr = sA + st * STG +
                    (unsigned)(((wm + im * 16 + arow) * 40 + kb + acol) * 2);
                LDSM_X4(af[im][0], af[im][1], af[im][2], af[im][3], addr);
            }
            #pragma unroll
            for (int np = 0; np < 2; np++) {
                unsigned addr = sB + st * STG +
                    (unsigned)(((wn + np * 16 + brow) * 40 + kb + bcol) * 2);
                LDSM_X4(bf[2 * np][0], bf[2 * np][1], bf[2 * np + 1][0], bf[2 * np + 1][1], addr);
            }
            #pragma unroll
            for (int im = 0; im < 4; im++)
                #pragma unroll
                for (int in_ = 0; in_ < 4; in_++)
                    mma_bf16(acc[im][in_], af[im], bf[in_]);
        }
        __syncthreads();
        if (kt + 2 < 8) { load_tile(st, (kt + 2) * 32); CP_COMMIT(); }
    }

    #pragma unroll
    for (int im = 0; im < 4; im++) {
        int row = m0 + wm + im * 16 + g;
        #pragma unroll
        for (int in_ = 0; in_ < 4; in_++) {
            int col = n0 + wn + in_ * 8 + 2 * c;
            float b0 = bias[col], b1 = bias[col + 1];
            float v00 = acc[im][in_][0] + b0, v01 = acc[im][in_][1] + b1;
            float v10 = acc[im][in_][2] + b0, v11 = acc[im][in_][3] + b1;
            if (Cf) {
                *(float2*)&Cf[(size_t)row * 256 + col]       = make_float2(v00, v01);
                *(float2*)&Cf[(size_t)(row + 8) * 256 + col] = make_float2(v10, v11);
            } else {
                *(__nv_bfloat162*)&Cb[(size_t)row * 256 + col] =
                    __float22bfloat162_rn(make_float2(v00, v01));
                *(__nv_bfloat162*)&Cb[(size_t)(row + 8) * 256 + col] =
                    __float22bfloat162_rn(make_float2(v10, v11));
            }
        }
    }
}

// QKV fused: grid (ROWS/128, 6). blockIdx.y selects {q,k,v} x {n-half}.
__global__ __launch_bounds__(256) void gemm_qkv_kernel(
    const __nv_bfloat16* __restrict__ xb,
    const __nv_bfloat16* __restrict__ wq, const __nv_bfloat16* __restrict__ wk,
    const __nv_bfloat16* __restrict__ wv,
    const float* __restrict__ bq, const float* __restrict__ bk,
    const float* __restrict__ bv,
    __nv_bfloat16* __restrict__ qb, __nv_bfloat16* __restrict__ kb,
    __nv_bfloat16* __restrict__ vb)
{
    const int sel = blockIdx.y >> 1;
    const int n0  = (blockIdx.y & 1) * 128;
    const __nv_bfloat16* W = (sel == 0) ? wq : (sel == 1) ? wk : wv;
    const float* bias      = (sel == 0) ? bq : (sel == 1) ? bk : bv;
    __nv_bfloat16* C       = (sel == 0) ? qb : (sel == 1) ? kb : vb;
    gemm_core(xb, W, bias, C, nullptr, blockIdx.x * 128, n0);
}

__global__ __launch_bounds__(256) void gemm_fc_kernel(
    const __nv_bfloat16* __restrict__ ab, const __nv_bfloat16* __restrict__ wf,
    const float* __restrict__ bias, float* __restrict__ fc)
{
    gemm_core(ab, wf, bias, nullptr, fc, blockIdx.x * 128, blockIdx.y * 128);
}

// ----------------------------------------------------------------------------
// Attention v4: tensor-core per-warp, bf16 in / bf16 out. (unchanged from R6)
// ----------------------------------------------------------------------------
#define QS_STRIDE 264
#define PS_STRIDE 28

__global__ __launch_bounds__(256) void attn_kernel(
    const __nv_bfloat16* __restrict__ Q, const __nv_bfloat16* __restrict__ K,
    const __nv_bfloat16* __restrict__ V,
    const float* __restrict__ mem_k, const float* __restrict__ mem_v,
    const float* __restrict__ alpha_l, __nv_bfloat16* __restrict__ out)
{
    __shared__ float Qs[Tt * QS_STRIDE];
    __shared__ float Ks[Tt * QS_STRIDE];
    __shared__ float Vs[Tt * QS_STRIDE];
    __shared__ float Ps[Hh][Tt * PS_STRIDE];

    const int tid  = threadIdx.x;
    const int lane = tid & 31;
    const int h    = tid >> 5;        // head
    const int g    = lane >> 2;       // 0..7
    const int c    = lane & 3;        // 0..3
    const int hc   = h * DK;
    const size_t base = (size_t)blockIdx.x * (Tt * Dd);

    for (int i = tid; i < Tt * 32; i += 256) {
        int r = i >> 5, c8 = (i & 31) * 8;
        uint4 qu = *(const uint4*)&Q[base + r * 256 + c8];
        uint4 ku = *(const uint4*)&K[base + r * 256 + c8];
        uint4 vu = *(const uint4*)&V[base + r * 256 + c8];
        const __nv_bfloat162* qp = (const __nv_bfloat162*)&qu;
        const __nv_bfloat162* kp = (const __nv_bfloat162*)&ku;
        const __nv_bfloat162* vp = (const __nv_bfloat162*)&vu;
        #pragma unroll
        for (int j = 0; j < 4; j++) {
            float2 qf = __bfloat1622float2(qp[j]);
            float2 kf = __bfloat1622float2(kp[j]);
            float2 vf = __bfloat1622float2(vp[j]);
            *(float2*)&Qs[r * QS_STRIDE + c8 + 2 * j] = qf;
            *(float2*)&Ks[r * QS_STRIDE + c8 + 2 * j] = kf;
            *(float2*)&Vs[r * QS_STRIDE + c8 + 2 * j] = vf;
        }
    }
    __syncthreads();

    float s0[4] = {0.f, 0.f, 0.f, 0.f};
    float s1[4] = {0.f, 0.f, 0.f, 0.f};
    float sm[4] = {0.f, 0.f, 0.f, 0.f};
    #pragma unroll
    for (int kk = 0; kk < 4; kk++) {
        const int kb = hc + kk * 8;
        unsigned a[4];
        a[0] = __float_as_uint(Qs[g * QS_STRIDE + kb + c]);
        a[1] = (g < 4) ? __float_as_uint(Qs[(g + 8) * QS_STRIDE + kb + c]) : 0u;
        a[2] = __float_as_uint(Qs[g * QS_STRIDE + kb + c + 4]);
        a[3] = (g < 4) ? __float_as_uint(Qs[(g + 8) * QS_STRIDE + kb + c + 4]) : 0u;
        unsigned b0[2], b1[2], bm[2];
        b0[0] = __float_as_uint(Ks[g * QS_STRIDE + kb + c]);
        b0[1] = __float_as_uint(Ks[g * QS_STRIDE + kb + c + 4]);
        b1[0] = (g < 4) ? __float_as_uint(Ks[(g + 8) * QS_STRIDE + kb + c]) : 0u;
        b1[1] = (g < 4) ? __float_as_uint(Ks[(g + 8) * QS_STRIDE + kb + c + 4]) : 0u;
        bm[0] = f2tf32(__ldg(&mem_k[(h * Mm + g) * DK + kk * 8 + c]));
        bm[1] = f2tf32(__ldg(&mem_k[(h * Mm + g) * DK + kk * 8 + c + 4]));
        mma_tf32(s0, a, b0);
        mma_tf32(s1, a, b1);
        mma_tf32(sm, a, bm);
    }

    const float scale = 0.1767766952966369f;
    const int s00 = 2 * c, s01 = 2 * c + 1, s10 = 8 + 2 * c, s11 = 8 + 2 * c + 1;
    const int tlo = g, thi = g + 8;
    float e[8];
    e[0] = (s00 <= tlo) ? s0[0] * scale : -1e30f;
    e[1] = (s01 <= tlo) ? s0[1] * scale : -1e30f;
    e[2] = (s10 <= tlo) ? s1[0] * scale : -1e30f;
    e[3] = (s11 <= tlo) ? s1[1] * scale : -1e30f;
    e[4] = (s00 <= thi) ? s0[2] * scale : -1e30f;
    e[5] = (s01 <= thi) ? s0[3] * scale : -1e30f;
    e[6] = (s10 <= thi) ? s1[2] * scale : -1e30f;
    e[7] = (s11 <= thi) ? s1[3] * scale : -1e30f;

    float mlo = fmaxf(fmaxf(e[0], e[1]), fmaxf(e[2], e[3]));
    float mhi = fmaxf(fmaxf(e[4], e[5]), fmaxf(e[6], e[7]));
    mlo = fmaxf(mlo, __shfl_xor_sync(0xffffffffu, mlo, 1));
    mlo = fmaxf(mlo, __shfl_xor_sync(0xffffffffu, mlo, 2));
    mhi = fmaxf(mhi, __shfl_xor_sync(0xffffffffu, mhi, 1));
    mhi = fmaxf(mhi, __shfl_xor_sync(0xffffffffu, mhi, 2));
    #pragma unroll
    for (int j = 0; j < 4; j++) e[j] = __expf(e[j] - mlo);
    #pragma unroll
    for (int j = 4; j < 8; j++) e[j] = __expf(e[j] - mhi);
    float slo = e[0] + e[1] + e[2] + e[3];
    float shi = e[4] + e[5] + e[6] + e[7];
    slo += __shfl_xor_sync(0xffffffffu, slo, 1);
    slo += __shfl_xor_sync(0xffffffffu, slo, 2);
    shi += __shfl_xor_sync(0xffffffffu, shi, 1);
    shi += __shfl_xor_sync(0xffffffffu, shi, 2);
    float rlo = 1.f / slo, rhi = 1.f / shi;
    #pragma unroll
    for (int j = 0; j < 4; j++) e[j] *= rlo;
    #pragma unroll
    for (int j = 4; j < 8; j++) e[j] *= rhi;

    float em[4];
    em[0] = sm[0] * scale; em[1] = sm[1] * scale;
    em[2] = sm[2] * scale; em[3] = sm[3] * scale;
    float mmlo = fmaxf(em[0], em[1]);
    float mmhi = fmaxf(em[2], em[3]);
    mmlo = fmaxf(mmlo, __shfl_xor_sync(0xffffffffu, mmlo, 1));
    mmlo = fmaxf(mmlo, __shfl_xor_sync(0xffffffffu, mmlo, 2));
    mmhi = fmaxf(mmhi, __shfl_xor_sync(0xffffffffu, mmhi, 1));
    mmhi = fmaxf(mmhi, __shfl_xor_sync(0xffffffffu, mmhi, 2));
    em[0] = __expf(em[0] - mmlo); em[1] = __expf(em[1] - mmlo);
    em[2] = __expf(em[2] - mmhi); em[3] = __expf(em[3] - mmhi);
    float smlo = em[0] + em[1];
    float smhi = em[2] + em[3];
    smlo += __shfl_xor_sync(0xffffffffu, smlo, 1);
    smlo += __shfl_xor_sync(0xffffffffu, smlo, 2);
    smhi += __shfl_xor_sync(0xffffffffu, smhi, 1);
    smhi += __shfl_xor_sync(0xffffffffu, smhi, 2);
    em[0] *= 1.f / smlo; em[1] *= 1.f / smlo;
    em[2] *= 1.f / smhi; em[3] *= 1.f / smhi;

    float* Pw = Ps[h];
    Pw[tlo * PS_STRIDE + s00] = __uint_as_float(f2tf32(e[0]));
    Pw[tlo * PS_STRIDE + s01] = __uint_as_float(f2tf32(e[1]));
    Pw[tlo * PS_STRIDE + s10] = __uint_as_float(f2tf32(e[2]));
    Pw[tlo * PS_STRIDE + s11] = __uint_as_float(f2tf32(e[3]));
    Pw[tlo * PS_STRIDE + 16 + s00] = __uint_as_float(f2tf32(em[0]));
    Pw[tlo * PS_STRIDE + 16 + s01] = __uint_as_float(f2tf32(em[1]));
    if (g < 4) {
        Pw[thi * PS_STRIDE + s00] = __uint_as_float(f2tf32(e[4]));
        Pw[thi * PS_STRIDE + s01] = __uint_as_float(f2tf32(e[5]));
        Pw[thi * PS_STRIDE + s10] = __uint_as_float(f2tf32(e[6]));
        Pw[thi * PS_STRIDE + s11] = __uint_as_float(f2tf32(e[7]));
        Pw[thi * PS_STRIDE + 16 + s00] = __uint_as_float(f2tf32(em[2]));
        Pw[thi * PS_STRIDE + 16 + s01] = __uint_as_float(f2tf32(em[3]));
    }
    __syncwarp();

    float o[4][4], l[4][4];
    #pragma unroll
    for (int nt = 0; nt < 4; nt++)
        #pragma unroll
        for (int r = 0; r < 4; r++) { o[nt][r] = 0.f; l[nt][r] = 0.f; }

    #pragma unroll
    for (int kk = 0; kk < 2; kk++) {
        unsigned pa[4];
        pa[0] = __float_as_uint(Pw[g * PS_STRIDE + kk * 8 + c]);
        pa[1] = (g < 4) ? __float_as_uint(Pw[(g + 8) * PS_STRIDE + kk * 8 + c]) : 0u;
        pa[2] = __float_as_uint(Pw[g * PS_STRIDE + kk * 8 + c + 4]);
        pa[3] = (g < 4) ? __float_as_uint(Pw[(g + 8) * PS_STRIDE + kk * 8 + c + 4]) : 0u;
        const int k0i = kk * 8 + c;
        const int k1i = kk * 8 + c + 4;
        #pragma unroll
        for (int nt = 0; nt < 4; nt++) {
            unsigned vb[2];
            vb[0] = __float_as_uint(Vs[k0i * QS_STRIDE + hc + nt * 8 + g]);
            vb[1] = (k1i < Tt) ? __float_as_uint(Vs[k1i * QS_STRIDE + hc + nt * 8 + g]) : 0u;
            mma_tf32(o[nt], pa, vb);
        }
    }
    {
        unsigned pa[4];
        pa[0] = __float_as_uint(Pw[g * PS_STRIDE + 16 + c]);
        pa[1] = (g < 4) ? __float_as_uint(Pw[(g + 8) * PS_STRIDE + 16 + c]) : 0u;
        pa[2] = __float_as_uint(Pw[g * PS_STRIDE + 16 + c + 4]);
        pa[3] = (g < 4) ? __float_as_uint(Pw[(g + 8) * PS_STRIDE + 16 + c + 4]) : 0u;
        #pragma unroll
        for (int nt = 0; nt < 4; nt++) {
            unsigned mb[2];
            mb[0] = f2tf32(__ldg(&mem_v[(h * Mm + c) * DK + nt * 8 + g]));
            mb[1] = f2tf32(__ldg(&mem_v[(h * Mm + c + 4) * DK + nt * 8 + g]));
            mma_tf32(l[nt], pa, mb);
        }
    }

    const float wl = 1.f / (1.f + __expf(-alpha_l[0]));
    const float wt = 1.f - wl;
    #pragma unroll
    for (int nt = 0; nt < 4; nt++) {
        int col = hc + nt * 8 + 2 * c;
        *(__nv_bfloat162*)&out[base + tlo * 256 + col] = __float22bfloat162_rn(
            make_float2(wt * o[nt][0] + wl * l[nt][0], wt * o[nt][1] + wl * l[nt][1]));
        if (g < 4) {
            *(__nv_bfloat162*)&out[base + thi * 256 + col] = __float22bfloat162_rn(
                make_float2(wt * o[nt][2] + wl * l[nt][2], wt * o[nt][3] + wl * l[nt][3]));
        }
    }
}

// ----------------------------------------------------------------------------
// Residual + LayerNorm: one warp per row (256 elems), float4 loads.
// ----------------------------------------------------------------------------
__global__ __launch_bounds__(256) void ln_kernel(
    const float* __restrict__ fcout, const float* __restrict__ x,
    const float* __restrict__ gamma, const float* __restrict__ beta,
    float* __restrict__ out)
{
    const int tid = threadIdx.x;
    const int lane = tid & 31;
    const int wrp = tid >> 5;
    const size_t row = (size_t)blockIdx.x * 8 + wrp;

    const float4* f4 = (const float4*)&fcout[row * 256];
    const float4* x4 = (const float4*)&x[row * 256];
    float4 a0 = f4[lane], a1 = f4[lane + 32];
    float4 b0 = x4[lane], b1 = x4[lane + 32];
    float4 v0 = make_float4(a0.x + b0.x, a0.y + b0.y, a0.z + b0.z, a0.w + b0.w);
    float4 v1 = make_float4(a1.x + b1.x, a1.y + b1.y, a1.z + b1.z, a1.w + b1.w);

    float s  = v0.x + v0.y + v0.z + v0.w + v1.x + v1.y + v1.z + v1.w;
    float s2 = v0.x*v0.x + v0.y*v0.y + v0.z*v0.z + v0.w*v0.w
             + v1.x*v1.x + v1.y*v1.y + v1.z*v1.z + v1.w*v1.w;
    #pragma unroll
    for (int o = 16; o > 0; o >>= 1) {
        s  += __shfl_xor_sync(0xffffffffu, s, o);
        s2 += __shfl_xor_sync(0xffffffffu, s2, o);
    }
    float mu = s * (1.f / 256.f);
    float var = s2 * (1.f / 256.f) - mu * mu;
    float rstd = rsqrtf(var + 1e-5f);

    const float4* g4 = (const float4*)gamma;
    const float4* be4 = (const float4*)beta;
    float4 g0 = g4[lane], g1 = g4[lane + 32];
    float4 e0 = be4[lane], e1 = be4[lane + 32];
    float4 o0, o1;
    o0.x = (v0.x - mu) * rstd * g0.x + e0.x;
    o0.y = (v0.y - mu) * rstd * g0.y + e0.y;
    o0.z = (v0.z - mu) * rstd * g0.z + e0.z;
    o0.w = (v0.w - mu) * rstd * g0.w + e0.w;
    o1.x = (v1.x - mu) * rstd * g1.x + e1.x;
    o1.y = (v1.y - mu) * rstd * g1.y + e1.y;
    o1.z = (v1.z - mu) * rstd * g1.z + e1.z;
    o1.w = (v1.w - mu) * rstd * g1.w + e1.w;
    float4* o4 = (float4*)&out[row * 256];
    o4[lane] = o0;
    o4[lane + 32] = o1;
}

// ----------------------------------------------------------------------------
// Launch
// ----------------------------------------------------------------------------
extern "C" void kernel_launch(void* const* d_in, const int* in_sizes, int n_in,
                              void* d_out, int out_size)
{
    const float* x     = (const float*)d_in[0];
    const float* Wq_w  = (const float*)d_in[1];
    const float* Wq_b  = (const float*)d_in[2];
    const float* Wk_w  = (const float*)d_in[3];
    const float* Wk_b  = (const float*)d_in[4];
    const float* Wv_w  = (const float*)d_in[5];
    const float* Wv_b  = (const float*)d_in[6];
    const float* mem_k = (const float*)d_in[7];
    const float* mem_v = (const float*)d_in[8];
    const float* fc_w  = (const float*)d_in[9];
    const float* fc_b  = (const float*)d_in[10];
    const float* gamma = (const float*)d_in[11];
    const float* beta  = (const float*)d_in[12];
    const float* alpha = (const float*)d_in[13];
    float* out = (float*)d_out;

    __nv_bfloat16 *xb, *qb, *kb, *vb, *ab, *wq, *wk, *wv, *wf;
    float* fc;
    cudaGetSymbolAddress((void**)&xb, g_xb);
    cudaGetSymbolAddress((void**)&qb, g_qb);
    cudaGetSymbolAddress((void**)&kb, g_kb);
    cudaGetSymbolAddress((void**)&vb, g_vb);
    cudaGetSymbolAddress((void**)&ab, g_ab);
    cudaGetSymbolAddress((void**)&fc, g_fc);
    cudaGetSymbolAddress((void**)&wq, g_wq);
    cudaGetSymbolAddress((void**)&wk, g_wk);
    cudaGetSymbolAddress((void**)&wv, g_wv);
    cudaGetSymbolAddress((void**)&wf, g_wf);

    const int xn4 = ROWS * Dd / 4;
    const int wn4 = Dd * Dd / 4;
    cvt_kernel<<<(xn4 + 255) / 256, 256>>>(x, xb, xn4);
    cvt_kernel<<<(wn4 + 255) / 256, 256>>>(Wq_w, wq, wn4);
    cvt_kernel<<<(wn4 + 255) / 256, 256>>>(Wk_w, wk, wn4);
    cvt_kernel<<<(wn4 + 255) / 256, 256>>>(Wv_w, wv, wn4);
    cvt_kernel<<<(wn4 + 255) / 256, 256>>>(fc_w, wf, wn4);

    dim3 qkv_grid(ROWS / 128, 6);
    gemm_qkv_kernel<<<qkv_grid, 256>>>(xb, wq, wk, wv, Wq_b, Wk_b, Wv_b, qb, kb, vb);

    attn_kernel<<<BN_CNT, 256>>>(qb, kb, vb, mem_k, mem_v, alpha, ab);

    dim3 fc_grid(ROWS / 128, 2);
    gemm_fc_kernel<<<fc_grid, 256>>>(ab, wf, fc_b, fc);

    ln_kernel<<<ROWS / 8, 256>>>(fc, x, gamma, beta, out);
}

// round 8
// speedup vs baseline: 5.3710x; 1.0531x over previous
#include <cuda_runtime.h>
#include <cuda_bf16.h>
#include <math.h>

#define Bb 8
#define Nn 2048
#define Tt 12
#define Dd 256
#define Hh 8
#define DK 32
#define Mm 8
#define ROWS (Bb * Nn * Tt)          // 196608
#define BN_CNT (Bb * Nn)             // 16384

// Scratch (device globals; allocation-free rule)
__device__ __nv_bfloat16 g_xb[ROWS * Dd];
__device__ __nv_bfloat16 g_qb[ROWS * Dd];
__device__ __nv_bfloat16 g_kb[ROWS * Dd];
__device__ __nv_bfloat16 g_vb[ROWS * Dd];
__device__ __nv_bfloat16 g_ab[ROWS * Dd];
__device__ __nv_bfloat16 g_wq[Dd * Dd];
__device__ __nv_bfloat16 g_wk[Dd * Dd];
__device__ __nv_bfloat16 g_wv[Dd * Dd];
__device__ __nv_bfloat16 g_wf[Dd * Dd];

#define CP_ASYNC16(dst, src) \
    asm volatile("cp.async.cg.shared.global [%0], [%1], 16;" :: "r"(dst), "l"(src))
#define CP_COMMIT() asm volatile("cp.async.commit_group;")
#define CP_WAIT(n)  asm volatile("cp.async.wait_group %0;" :: "n"(n))

#define LDSM_X4(r0, r1, r2, r3, addr) \
    asm volatile("ldmatrix.sync.aligned.m8n8.x4.shared.b16 {%0,%1,%2,%3}, [%4];" \
        : "=r"(r0), "=r"(r1), "=r"(r2), "=r"(r3) : "r"(addr))

__device__ __forceinline__ unsigned f2tf32(float f) {
    unsigned u;
    asm("cvt.rna.tf32.f32 %0, %1;" : "=r"(u) : "f"(f));
    return u;
}

__device__ __forceinline__ void mma_tf32(float* c, const unsigned* a, const unsigned* b) {
    asm volatile(
        "mma.sync.aligned.m16n8k8.row.col.f32.tf32.tf32.f32 "
        "{%0,%1,%2,%3}, {%4,%5,%6,%7}, {%8,%9}, {%0,%1,%2,%3};"
        : "+f"(c[0]), "+f"(c[1]), "+f"(c[2]), "+f"(c[3])
        : "r"(a[0]), "r"(a[1]), "r"(a[2]), "r"(a[3]), "r"(b[0]), "r"(b[1]));
}

__device__ __forceinline__ void mma_bf16(float* c, const unsigned* a, const unsigned* b) {
    asm volatile(
        "mma.sync.aligned.m16n8k16.row.col.f32.bf16.bf16.f32 "
        "{%0,%1,%2,%3}, {%4,%5,%6,%7}, {%8,%9}, {%0,%1,%2,%3};"
        : "+f"(c[0]), "+f"(c[1]), "+f"(c[2]), "+f"(c[3])
        : "r"(a[0]), "r"(a[1]), "r"(a[2]), "r"(a[3]), "r"(b[0]), "r"(b[1]));
}

// ----------------------------------------------------------------------------
// fp32 -> bf16 conversions
// ----------------------------------------------------------------------------
__global__ __launch_bounds__(256) void cvt_kernel(
    const float* __restrict__ in, __nv_bfloat16* __restrict__ out, int n4)
{
    int i = blockIdx.x * 256 + threadIdx.x;
    if (i < n4) {
        float4 v = ((const float4*)in)[i];
        ((__nv_bfloat162*)out)[2 * i]     = __float22bfloat162_rn(make_float2(v.x, v.y));
        ((__nv_bfloat162*)out)[2 * i + 1] = __float22bfloat162_rn(make_float2(v.z, v.w));
    }
}

__global__ __launch_bounds__(256) void cvt_w_kernel(
    const float* __restrict__ w0, const float* __restrict__ w1,
    const float* __restrict__ w2, const float* __restrict__ w3,
    __nv_bfloat16* __restrict__ d0, __nv_bfloat16* __restrict__ d1,
    __nv_bfloat16* __restrict__ d2, __nv_bfloat16* __restrict__ d3)
{
    const int sel = blockIdx.y;
    const float* in = (sel == 0) ? w0 : (sel == 1) ? w1 : (sel == 2) ? w2 : w3;
    __nv_bfloat16* out = (sel == 0) ? d0 : (sel == 1) ? d1 : (sel == 2) ? d2 : d3;
    int i = blockIdx.x * 256 + threadIdx.x;   // n4 = 16384 = 64 blocks exact
    float4 v = ((const float4*)in)[i];
    ((__nv_bfloat162*)out)[2 * i]     = __float22bfloat162_rn(make_float2(v.x, v.y));
    ((__nv_bfloat162*)out)[2 * i + 1] = __float22bfloat162_rn(make_float2(v.z, v.w));
}

// ----------------------------------------------------------------------------
// GEMM core (QKV): BM=BN=128, BK=32, 2-stage cp.async, ldmatrix. (R7, proven)
// ----------------------------------------------------------------------------
__device__ __forceinline__ void gemm_core(
    const __nv_bfloat16* __restrict__ A, const __nv_bfloat16* __restrict__ W,
    const float* __restrict__ bias, __nv_bfloat16* __restrict__ Cb, int m0, int n0)
{
    __shared__ __nv_bfloat16 As[2][128][40];
    __shared__ __nv_bfloat16 Bs[2][128][40];

    const int tid  = threadIdx.x;
    const int lane = tid & 31;
    const int wid  = tid >> 5;
    const int wm   = (wid >> 2) * 64;
    const int wn   = (wid & 3) * 32;
    const int g    = lane >> 2;
    const int c    = lane & 3;

    float acc[4][4][4];
    #pragma unroll
    for (int i = 0; i < 4; i++)
        #pragma unroll
        for (int j = 0; j < 4; j++)
            #pragma unroll
            for (int r = 0; r < 4; r++) acc[i][j][r] = 0.f;

    const int idx0 = tid * 2;
    const int r0   = idx0 >> 2;
    const int h0   = (idx0 & 3) << 3;
    const int idx1 = idx0 + 1;
    const int r1   = idx1 >> 2;
    const int h1   = (idx1 & 3) << 3;

    const unsigned sA = (unsigned)__cvta_generic_to_shared(&As[0][0][0]);
    const unsigned sB = (unsigned)__cvta_generic_to_shared(&Bs[0][0][0]);
    const unsigned STG = 128 * 40 * 2;

    auto load_tile = [&](int st, int k0) {
        CP_ASYNC16(sA + st * STG + (r0 * 40 + h0) * 2, &A[(size_t)(m0 + r0) * 256 + k0 + h0]);
        CP_ASYNC16(sB + st * STG + (r0 * 40 + h0) * 2, &W[(size_t)(n0 + r0) * 256 + k0 + h0]);
        CP_ASYNC16(sA + st * STG + (r1 * 40 + h1) * 2, &A[(size_t)(m0 + r1) * 256 + k0 + h1]);
        CP_ASYNC16(sB + st * STG + (r1 * 40 + h1) * 2, &W[(size_t)(n0 + r1) * 256 + k0 + h1]);
    };

    const int arow = lane & 15;
    const int acol = (lane >> 4) << 3;
    const int brow = (lane & 7) + ((lane >> 4) << 3);
    const int bcol = ((lane >> 3) & 1) << 3;

    load_tile(0, 0);  CP_COMMIT();
    load_tile(1, 32); CP_COMMIT();

    #pragma unroll
    for (int kt = 0; kt < 8; kt++) {
        const int st = kt & 1;
        if (kt == 7) { CP_WAIT(0); } else { CP_WAIT(1); }
        __syncthreads();

        #pragma unroll
        for (int kk = 0; kk < 2; kk++) {
            const int kb = kk * 16;
            unsigned af[4][4];
            unsigned bf[4][2];
            #pragma unroll
            for (int im = 0; im < 4; im++) {
                unsigned addr = sA + st * STG +
                    (unsigned)(((wm + im * 16 + arow) * 40 + kb + acol) * 2);
                LDSM_X4(af[im][0], af[im][1], af[im][2], af[im][3], addr);
            }
            #pragma unroll
            for (int np = 0; np < 2; np++) {
                unsigned addr = sB + st * STG +
                    (unsigned)(((wn + np * 16 + brow) * 40 + kb + bcol) * 2);
                LDSM_X4(bf[2 * np][0], bf[2 * np][1], bf[2 * np + 1][0], bf[2 * np + 1][1], addr);
            }
            #pragma unroll
            for (int im = 0; im < 4; im++)
                #pragma unroll
                for (int in_ = 0; in_ < 4; in_++)
                    mma_bf16(acc[im][in_], af[im], bf[in_]);
        }
        __syncthreads();
        if (kt + 2 < 8) { load_tile(st, (kt + 2) * 32); CP_COMMIT(); }
    }

    #pragma unroll
    for (int im = 0; im < 4; im++) {
        int row = m0 + wm + im * 16 + g;
        #pragma unroll
        for (int in_ = 0; in_ < 4; in_++) {
            int col = n0 + wn + in_ * 8 + 2 * c;
            float b0 = bias[col], b1 = bias[col + 1];
            *(__nv_bfloat162*)&Cb[(size_t)row * 256 + col] =
                __float22bfloat162_rn(make_float2(acc[im][in_][0] + b0, acc[im][in_][1] + b1));
            *(__nv_bfloat162*)&Cb[(size_t)(row + 8) * 256 + col] =
                __float22bfloat162_rn(make_float2(acc[im][in_][2] + b0, acc[im][in_][3] + b1));
        }
    }
}

__global__ __launch_bounds__(256) void gemm_qkv_kernel(
    const __nv_bfloat16* __restrict__ xb,
    const __nv_bfloat16* __restrict__ wq, const __nv_bfloat16* __restrict__ wk,
    const __nv_bfloat16* __restrict__ wv,
    const float* __restrict__ bq, const float* __restrict__ bk,
    const float* __restrict__ bv,
    __nv_bfloat16* __restrict__ qb, __nv_bfloat16* __restrict__ kb,
    __nv_bfloat16* __restrict__ vb)
{
    const int sel = blockIdx.y >> 1;
    const int n0  = (blockIdx.y & 1) * 128;
    const __nv_bfloat16* W = (sel == 0) ? wq : (sel == 1) ? wk : wv;
    const float* bias      = (sel == 0) ? bq : (sel == 1) ? bk : bv;
    __nv_bfloat16* C       = (sel == 0) ? qb : (sel == 1) ? kb : vb;
    gemm_core(xb, W, bias, C, blockIdx.x * 128, n0);
}

// ----------------------------------------------------------------------------
// Fused FC GEMM + residual + LayerNorm.
// BM=128, BN=256 (full row per CTA), BK=16, 2-stage cp.async, ldmatrix.
// 8 warps, warp tile 64x64. Epilogue: v = acc + bias + x; deterministic
// per-row reduction (quad shfl -> per-warp smem partials -> finalize); LN store.
// ----------------------------------------------------------------------------
#define FSTR 24   // halfs per smem row (16 used + 8 pad = 48B, 16B-aligned)

__global__ __launch_bounds__(256) void gemm_fc_ln_kernel(
    const __nv_bfloat16* __restrict__ A, const __nv_bfloat16* __restrict__ W,
    const float* __restrict__ bias, const float* __restrict__ x,
    const float* __restrict__ gamma, const float* __restrict__ beta,
    float* __restrict__ out)
{
    __shared__ __nv_bfloat16 As[2][128][FSTR];
    __shared__ __nv_bfloat16 Bs[2][256][FSTR];
    __shared__ float psum[8][64];
    __shared__ float psum2[8][64];
    __shared__ float smu[128];
    __shared__ float srstd[128];

    const int tid  = threadIdx.x;
    const int lane = tid & 31;
    const int wid  = tid >> 5;
    const int wm   = (wid >> 2) * 64;   // 0 or 64 (row half)
    const int wn   = (wid & 3) * 64;    // 0,64,128,192
    const int m0   = blockIdx.x * 128;
    const int g    = lane >> 2;
    const int c    = lane & 3;

    float acc[4][8][4];
    #pragma unroll
    for (int i = 0; i < 4; i++)
        #pragma unroll
        for (int j = 0; j < 8; j++)
            #pragma unroll
            for (int r = 0; r < 4; r++) acc[i][j][r] = 0.f;

    // load map: per stage 256 A-chunks + 512 B-chunks of 16B; 3 per thread
    const int rA = tid >> 1;
    const int cC = (tid & 1) << 3;      // 0 or 8 (halfs)

    const unsigned sA = (unsigned)__cvta_generic_to_shared(&As[0][0][0]);
    const unsigned sB = (unsigned)__cvta_generic_to_shared(&Bs[0][0][0]);
    const unsigned ASTG = 128 * FSTR * 2;
    const unsigned BSTG = 256 * FSTR * 2;

    auto load_tile = [&](int st, int k0) {
        CP_ASYNC16(sA + st * ASTG + (rA * FSTR + cC) * 2,
                   &A[(size_t)(m0 + rA) * 256 + k0 + cC]);
        CP_ASYNC16(sB + st * BSTG + (rA * FSTR + cC) * 2,
                   &W[(size_t)rA * 256 + k0 + cC]);
        CP_ASYNC16(sB + st * BSTG + ((128 + rA) * FSTR + cC) * 2,
                   &W[(size_t)(128 + rA) * 256 + k0 + cC]);
    };

    const int arow = lane & 15;
    const int acol = (lane >> 4) << 3;
    const int brow = (lane & 7) + ((lane >> 4) << 3);
    const int bcol = ((lane >> 3) & 1) << 3;

    load_tile(0, 0);  CP_COMMIT();
    load_tile(1, 16); CP_COMMIT();

    #pragma unroll
    for (int kt = 0; kt < 16; kt++) {
        const int st = kt & 1;
        if (kt == 15) { CP_WAIT(0); } else { CP_WAIT(1); }
        __syncthreads();

        unsigned af[4][4];
        unsigned bf[8][2];
        #pragma unroll
        for (int im = 0; im < 4; im++) {
            unsigned addr = sA + st * ASTG +
                (unsigned)(((wm + im * 16 + arow) * FSTR + acol) * 2);
            LDSM_X4(af[im][0], af[im][1], af[im][2], af[im][3], addr);
        }
        #pragma unroll
        for (int np = 0; np < 4; np++) {
            unsigned addr = sB + st * BSTG +
                (unsigned)(((wn + np * 16 + brow) * FSTR + bcol) * 2);
            LDSM_X4(bf[2 * np][0], bf[2 * np][1], bf[2 * np + 1][0], bf[2 * np + 1][1], addr);
        }
        #pragma unroll
        for (int im = 0; im < 4; im++)
            #pragma unroll
            for (int in_ = 0; in_ < 8; in_++)
                mma_bf16(acc[im][in_], af[im], bf[in_]);

        __syncthreads();
        if (kt + 2 < 16) { load_tile(st, (kt + 2) * 16); CP_COMMIT(); }
    }

    // ---- epilogue: v = acc + bias + x ; row sums; LN ----
    #pragma unroll
    for (int im = 0; im < 4; im++) {
        size_t row  = (size_t)(m0 + wm + im * 16 + g) * 256;
        size_t row2 = row + 8 * 256;
        float s1 = 0.f, q1 = 0.f, s2 = 0.f, q2 = 0.f;
        #pragma unroll
        for (int in_ = 0; in_ < 8; in_++) {
            int col = wn + in_ * 8 + 2 * c;
            float b0 = bias[col], b1 = bias[col + 1];
            float2 x0 = *(const float2*)&x[row + col];
            float2 x1 = *(const float2*)&x[row2 + col];
            float v00 = acc[im][in_][0] + b0 + x0.x;
            float v01 = acc[im][in_][1] + b1 + x0.y;
            float v10 = acc[im][in_][2] + b0 + x1.x;
            float v11 = acc[im][in_][3] + b1 + x1.y;
            acc[im][in_][0] = v00; acc[im][in_][1] = v01;
            acc[im][in_][2] = v10; acc[im][in_][3] = v11;
            s1 += v00 + v01; q1 += v00 * v00 + v01 * v01;
            s2 += v10 + v11; q2 += v10 * v10 + v11 * v11;
        }
        // quad reduce over c (lanes g*4+c)
        #pragma unroll
        for (int off = 1; off <= 2; off <<= 1) {
            s1 += __shfl_xor_sync(0xffffffffu, s1, off);
            q1 += __shfl_xor_sync(0xffffffffu, q1, off);
            s2 += __shfl_xor_sync(0xffffffffu, s2, off);
            q2 += __shfl_xor_sync(0xffffffffu, q2, off);
        }
        if (c == 0) {
            psum[wid][im * 16 + g]      = s1;
            psum2[wid][im * 16 + g]     = q1;
            psum[wid][im * 16 + g + 8]  = s2;
            psum2[wid][im * 16 + g + 8] = q2;
        }
    }
    __syncthreads();

    if (tid < 128) {
        const int half = tid >> 6;       // which row-half
        const int ri   = tid & 63;
        float s = 0.f, q = 0.f;
        #pragma unroll
        for (int j = 0; j < 4; j++) {
            s += psum[half * 4 + j][ri];
            q += psum2[half * 4 + j][ri];
        }
        float mu  = s * (1.f / 256.f);
        float var = q * (1.f / 256.f) - mu * mu;
        smu[tid]   = mu;
        srstd[tid] = rsqrtf(var + 1e-5f);
    }
    __syncthreads();

    #pragma unroll
    for (int im = 0; im < 4; im++) {
        int rl = wm + im * 16 + g;
        float mu1 = smu[rl],     rs1 = srstd[rl];
        float mu2 = smu[rl + 8], rs2 = srstd[rl + 8];
        size_t row  = (size_t)(m0 + rl) * 256;
        size_t row2 = row + 8 * 256;
        #pragma unroll
        for (int in_ = 0; in_ < 8; in_++) {
            int col = wn + in_ * 8 + 2 * c;
            float ga0 = gamma[col], ga1 = gamma[col + 1];
            float be0 = beta[col],  be1 = beta[col + 1];
            *(float2*)&out[row + col] = make_float2(
                (acc[im][in_][0] - mu1) * rs1 * ga0 + be0,
                (acc[im][in_][1] - mu1) * rs1 * ga1 + be1);
            *(float2*)&out[row2 + col] = make_float2(
                (acc[im][in_][2] - mu2) * rs2 * ga0 + be0,
                (acc[im][in_][3] - mu2) * rs2 * ga1 + be1);
        }
    }
}

// ----------------------------------------------------------------------------
// Attention v4: tensor-core per-warp, bf16 in / bf16 out. (R6/R7, proven)
// ----------------------------------------------------------------------------
#define QS_STRIDE 264
#define PS_STRIDE 28

__global__ __launch_bounds__(256) void attn_kernel(
    const __nv_bfloat16* __restrict__ Q, const __nv_bfloat16* __restrict__ K,
    const __nv_bfloat16* __restrict__ V,
    const float* __restrict__ mem_k, const float* __restrict__ mem_v,
    const float* __restrict__ alpha_l, __nv_bfloat16* __restrict__ out)
{
    __shared__ float Qs[Tt * QS_STRIDE];
    __shared__ float Ks[Tt * QS_STRIDE];
    __shared__ float Vs[Tt * QS_STRIDE];
    __shared__ float Ps[Hh][Tt * PS_STRIDE];

    const int tid  = threadIdx.x;
    const int lane = tid & 31;
    const int h    = tid >> 5;
    const int g    = lane >> 2;
    const int c    = lane & 3;
    const int hc   = h * DK;
    const size_t base = (size_t)blockIdx.x * (Tt * Dd);

    for (int i = tid; i < Tt * 32; i += 256) {
        int r = i >> 5, c8 = (i & 31) * 8;
        uint4 qu = *(const uint4*)&Q[base + r * 256 + c8];
        uint4 ku = *(const uint4*)&K[base + r * 256 + c8];
        uint4 vu = *(const uint4*)&V[base + r * 256 + c8];
        const __nv_bfloat162* qp = (const __nv_bfloat162*)&qu;
        const __nv_bfloat162* kp = (const __nv_bfloat162*)&ku;
        const __nv_bfloat162* vp = (const __nv_bfloat162*)&vu;
        #pragma unroll
        for (int j = 0; j < 4; j++) {
            *(float2*)&Qs[r * QS_STRIDE + c8 + 2 * j] = __bfloat1622float2(qp[j]);
            *(float2*)&Ks[r * QS_STRIDE + c8 + 2 * j] = __bfloat1622float2(kp[j]);
            *(float2*)&Vs[r * QS_STRIDE + c8 + 2 * j] = __bfloat1622float2(vp[j]);
        }
    }
    __syncthreads();

    float s0[4] = {0.f, 0.f, 0.f, 0.f};
    float s1[4] = {0.f, 0.f, 0.f, 0.f};
    float sm[4] = {0.f, 0.f, 0.f, 0.f};
    #pragma unroll
    for (int kk = 0; kk < 4; kk++) {
        const int kb = hc + kk * 8;
        unsigned a[4];
        a[0] = __float_as_uint(Qs[g * QS_STRIDE + kb + c]);
        a[1] = (g < 4) ? __float_as_uint(Qs[(g + 8) * QS_STRIDE + kb + c]) : 0u;
        a[2] = __float_as_uint(Qs[g * QS_STRIDE + kb + c + 4]);
        a[3] = (g < 4) ? __float_as_uint(Qs[(g + 8) * QS_STRIDE + kb + c + 4]) : 0u;
        unsigned b0[2], b1[2], bm[2];
        b0[0] = __float_as_uint(Ks[g * QS_STRIDE + kb + c]);
        b0[1] = __float_as_uint(Ks[g * QS_STRIDE + kb + c + 4]);
        b1[0] = (g < 4) ? __float_as_uint(Ks[(g + 8) * QS_STRIDE + kb + c]) : 0u;
        b1[1] = (g < 4) ? __float_as_uint(Ks[(g + 8) * QS_STRIDE + kb + c + 4]) : 0u;
        bm[0] = f2tf32(__ldg(&mem_k[(h * Mm + g) * DK + kk * 8 + c]));
        bm[1] = f2tf32(__ldg(&mem_k[(h * Mm + g) * DK + kk * 8 + c + 4]));
        mma_tf32(s0, a, b0);
        mma_tf32(s1, a, b1);
        mma_tf32(sm, a, bm);
    }

    const float scale = 0.1767766952966369f;
    const int s00 = 2 * c, s01 = 2 * c + 1, s10 = 8 + 2 * c, s11 = 8 + 2 * c + 1;
    const int tlo = g, thi = g + 8;
    float e[8];
    e[0] = (s00 <= tlo) ? s0[0] * scale : -1e30f;
    e[1] = (s01 <= tlo) ? s0[1] * scale : -1e30f;
    e[2] = (s10 <= tlo) ? s1[0] * scale : -1e30f;
    e[3] = (s11 <= tlo) ? s1[1] * scale : -1e30f;
    e[4] = (s00 <= thi) ? s0[2] * scale : -1e30f;
    e[5] = (s01 <= thi) ? s0[3] * scale : -1e30f;
    e[6] = (s10 <= thi) ? s1[2] * scale : -1e30f;
    e[7] = (s11 <= thi) ? s1[3] * scale : -1e30f;

    float mlo = fmaxf(fmaxf(e[0], e[1]), fmaxf(e[2], e[3]));
    float mhi = fmaxf(fmaxf(e[4], e[5]), fmaxf(e[6], e[7]));
    mlo = fmaxf(mlo, __shfl_xor_sync(0xffffffffu, mlo, 1));
    mlo = fmaxf(mlo, __shfl_xor_sync(0xffffffffu, mlo, 2));
    mhi = fmaxf(mhi, __shfl_xor_sync(0xffffffffu, mhi, 1));
    mhi = fmaxf(mhi, __shfl_xor_sync(0xffffffffu, mhi, 2));
    #pragma unroll
    for (int j = 0; j < 4; j++) e[j] = __expf(e[j] - mlo);
    #pragma unroll
    for (int j = 4; j < 8; j++) e[j] = __expf(e[j] - mhi);
    float slo = e[0] + e[1] + e[2] + e[3];
    float shi = e[4] + e[5] + e[6] + e[7];
    slo += __shfl_xor_sync(0xffffffffu, slo, 1);
    slo += __shfl_xor_sync(0xffffffffu, slo, 2);
    shi += __shfl_xor_sync(0xffffffffu, shi, 1);
    shi += __shfl_xor_sync(0xffffffffu, shi, 2);
    float rlo = 1.f / slo, rhi = 1.f / shi;
    #pragma unroll
    for (int j = 0; j < 4; j++) e[j] *= rlo;
    #pragma unroll
    for (int j = 4; j < 8; j++) e[j] *= rhi;

    float em[4];
    em[0] = sm[0] * scale; em[1] = sm[1] * scale;
    em[2] = sm[2] * scale; em[3] = sm[3] * scale;
    float mmlo = fmaxf(em[0], em[1]);
    float mmhi = fmaxf(em[2], em[3]);
    mmlo = fmaxf(mmlo, __shfl_xor_sync(0xffffffffu, mmlo, 1));
    mmlo = fmaxf(mmlo, __shfl_xor_sync(0xffffffffu, mmlo, 2));
    mmhi = fmaxf(mmhi, __shfl_xor_sync(0xffffffffu, mmhi, 1));
    mmhi = fmaxf(mmhi, __shfl_xor_sync(0xffffffffu, mmhi, 2));
    em[0] = __expf(em[0] - mmlo); em[1] = __expf(em[1] - mmlo);
    em[2] = __expf(em[2] - mmhi); em[3] = __expf(em[3] - mmhi);
    float smlo = em[0] + em[1];
    float smhi = em[2] + em[3];
    smlo += __shfl_xor_sync(0xffffffffu, smlo, 1);
    smlo += __shfl_xor_sync(0xffffffffu, smlo, 2);
    smhi += __shfl_xor_sync(0xffffffffu, smhi, 1);
    smhi += __shfl_xor_sync(0xffffffffu, smhi, 2);
    em[0] *= 1.f / smlo; em[1] *= 1.f / smlo;
    em[2] *= 1.f / smhi; em[3] *= 1.f / smhi;

    float* Pw = Ps[h];
    Pw[tlo * PS_STRIDE + s00] = __uint_as_float(f2tf32(e[0]));
    Pw[tlo * PS_STRIDE + s01] = __uint_as_float(f2tf32(e[1]));
    Pw[tlo * PS_STRIDE + s10] = __uint_as_float(f2tf32(e[2]));
    Pw[tlo * PS_STRIDE + s11] = __uint_as_float(f2tf32(e[3]));
    Pw[tlo * PS_STRIDE + 16 + s00] = __uint_as_float(f2tf32(em[0]));
    Pw[tlo * PS_STRIDE + 16 + s01] = __uint_as_float(f2tf32(em[1]));
    if (g < 4) {
        Pw[thi * PS_STRIDE + s00] = __uint_as_float(f2tf32(e[4]));
        Pw[thi * PS_STRIDE + s01] = __uint_as_float(f2tf32(e[5]));
        Pw[thi * PS_STRIDE + s10] = __uint_as_float(f2tf32(e[6]));
        Pw[thi * PS_STRIDE + s11] = __uint_as_float(f2tf32(e[7]));
        Pw[thi * PS_STRIDE + 16 + s00] = __uint_as_float(f2tf32(em[2]));
        Pw[thi * PS_STRIDE + 16 + s01] = __uint_as_float(f2tf32(em[3]));
    }
    __syncwarp();

    float o[4][4], l[4][4];
    #pragma unroll
    for (int nt = 0; nt < 4; nt++)
        #pragma unroll
        for (int r = 0; r < 4; r++) { o[nt][r] = 0.f; l[nt][r] = 0.f; }

    #pragma unroll
    for (int kk = 0; kk < 2; kk++) {
        unsigned pa[4];
        pa[0] = __float_as_uint(Pw[g * PS_STRIDE + kk * 8 + c]);
        pa[1] = (g < 4) ? __float_as_uint(Pw[(g + 8) * PS_STRIDE + kk * 8 + c]) : 0u;
        pa[2] = __float_as_uint(Pw[g * PS_STRIDE + kk * 8 + c + 4]);
        pa[3] = (g < 4) ? __float_as_uint(Pw[(g + 8) * PS_STRIDE + kk * 8 + c + 4]) : 0u;
        const int k0i = kk * 8 + c;
        const int k1i = kk * 8 + c + 4;
        #pragma unroll
        for (int nt = 0; nt < 4; nt++) {
            unsigned vb[2];
            vb[0] = __float_as_uint(Vs[k0i * QS_STRIDE + hc + nt * 8 + g]);
            vb[1] = (k1i < Tt) ? __float_as_uint(Vs[k1i * QS_STRIDE + hc + nt * 8 + g]) : 0u;
            mma_tf32(o[nt], pa, vb);
        }
    }
    {
        unsigned pa[4];
        pa[0] = __float_as_uint(Pw[g * PS_STRIDE + 16 + c]);
        pa[1] = (g < 4) ? __float_as_uint(Pw[(g + 8) * PS_STRIDE + 16 + c]) : 0u;
        pa[2] = __float_as_uint(Pw[g * PS_STRIDE + 16 + c + 4]);
        pa[3] = (g < 4) ? __float_as_uint(Pw[(g + 8) * PS_STRIDE + 16 + c + 4]) : 0u;
        #pragma unroll
        for (int nt = 0; nt < 4; nt++) {
            unsigned mb[2];
            mb[0] = f2tf32(__ldg(&mem_v[(h * Mm + c) * DK + nt * 8 + g]));
            mb[1] = f2tf32(__ldg(&mem_v[(h * Mm + c + 4) * DK + nt * 8 + g]));
            mma_tf32(l[nt], pa, mb);
        }
    }

    const float wl = 1.f / (1.f + __expf(-alpha_l[0]));
    const float wt = 1.f - wl;
    #pragma unroll
    for (int nt = 0; nt < 4; nt++) {
        int col = hc + nt * 8 + 2 * c;
        *(__nv_bfloat162*)&out[base + tlo * 256 + col] = __float22bfloat162_rn(
            make_float2(wt * o[nt][0] + wl * l[nt][0], wt * o[nt][1] + wl * l[nt][1]));
        if (g < 4) {
            *(__nv_bfloat162*)&out[base + thi * 256 + col] = __float22bfloat162_rn(
                make_float2(wt * o[nt][2] + wl * l[nt][2], wt * o[nt][3] + wl * l[nt][3]));
        }
    }
}

// ----------------------------------------------------------------------------
// Launch
// ----------------------------------------------------------------------------
extern "C" void kernel_launch(void* const* d_in, const int* in_sizes, int n_in,
                              void* d_out, int out_size)
{
    const float* x     = (const float*)d_in[0];
    const float* Wq_w  = (const float*)d_in[1];
    const float* Wq_b  = (const float*)d_in[2];
    const float* Wk_w  = (const float*)d_in[3];
    const float* Wk_b  = (const float*)d_in[4];
    const float* Wv_w  = (const float*)d_in[5];
    const float* Wv_b  = (const float*)d_in[6];
    const float* mem_k = (const float*)d_in[7];
    const float* mem_v = (const float*)d_in[8];
    const float* fc_w  = (const float*)d_in[9];
    const float* fc_b  = (const float*)d_in[10];
    const float* gamma = (const float*)d_in[11];
    const float* beta  = (const float*)d_in[12];
    const float* alpha = (const float*)d_in[13];
    float* out = (float*)d_out;

    __nv_bfloat16 *xb, *qb, *kb, *vb, *ab, *wq, *wk, *wv, *wf;
    cudaGetSymbolAddress((void**)&xb, g_xb);
    cudaGetSymbolAddress((void**)&qb, g_qb);
    cudaGetSymbolAddress((void**)&kb, g_kb);
    cudaGetSymbolAddress((void**)&vb, g_vb);
    cudaGetSymbolAddress((void**)&ab, g_ab);
    cudaGetSymbolAddress((void**)&wq, g_wq);
    cudaGetSymbolAddress((void**)&wk, g_wk);
    cudaGetSymbolAddress((void**)&wv, g_wv);
    cudaGetSymbolAddress((void**)&wf, g_wf);

    const int xn4 = ROWS * Dd / 4;
    cvt_kernel<<<(xn4 + 255) / 256, 256>>>(x, xb, xn4);
    dim3 wgrid(64, 4);
    cvt_w_kernel<<<wgrid, 256>>>(Wq_w, Wk_w, Wv_w, fc_w, wq, wk, wv, wf);

    dim3 qkv_grid(ROWS / 128, 6);
    gemm_qkv_kernel<<<qkv_grid, 256>>>(xb, wq, wk, wv, Wq_b, Wk_b, Wv_b, qb, kb, vb);

    attn_kernel<<<BN_CNT, 256>>>(qb, kb, vb, mem_k, mem_v, alpha, ab);

    gemm_fc_ln_kernel<<<ROWS / 128, 256>>>(ab, wf, fc_b, x, gamma, beta, out);
}